// round 2
// baseline (speedup 1.0000x reference)
#include <cuda_runtime.h>
#include <math.h>

#define T_STEPS 128
#define BATCH   256
#define DIN     256
#define DH      1024
#define DOUT    256

// Scratch: Z = xs@W1x + b1 for all timesteps, plus ping-pong h buffers.
__device__ float g_z[(size_t)T_STEPS * BATCH * DH];   // 134 MB
__device__ float g_h[2 * (size_t)BATCH * DH];         // 2 MB

// ---------------- packed f32x2 helpers (FFMA2 path) ----------------
__device__ __forceinline__ void fma2(unsigned long long& acc,
                                     unsigned long long a,
                                     unsigned long long b) {
    asm("fma.rn.f32x2 %0, %1, %2, %0;" : "+l"(acc) : "l"(a), "l"(b));
}
__device__ __forceinline__ unsigned long long pack2(float x, float y) {
    unsigned long long r;
    asm("mov.b64 %0, {%1, %2};" : "=l"(r) : "f"(x), "f"(y));
    return r;
}
__device__ __forceinline__ float2 unpack2(unsigned long long v) {
    float2 f;
    asm("mov.b64 {%0, %1}, %2;" : "=f"(f.x), "=f"(f.y) : "l"(v));
    return f;
}

struct alignas(16) U64x2 { unsigned long long x, y; };

// ---------------- zero-init kernel ----------------
__global__ void zero_kernel(float* __restrict__ p, int n) {
    int i = blockIdx.x * blockDim.x + threadIdx.x;
    if (i < n) p[i] = 0.0f;
}

// =====================================================================
// Specialized RNN step kernel: C = tanh(A@B + Z)
//   A [256,1024] (h), B = W1h [1024,1024], Z slice [256,1024]
// Tile 32x64, BK=32, 256 threads, TM=2 x TN=4 per thread.
// A stored DUPLICATED in shared ([a0,a0,a1,a1] quads) so the hot loop is
// exactly 2x LDS.128 + 4x FFMA2 per k, no packs.
// =====================================================================
#define SBM 32
#define SBN 64
#define SBK 32
#define SPAD 4

__global__ void __launch_bounds__(256, 1)
step_kernel(const float* __restrict__ A, const float* __restrict__ Bm,
            const float* __restrict__ Z, float* __restrict__ C) {
    __shared__ float As[2][SBK][2 * SBM + SPAD];  // duplicated A, 68-float rows
    __shared__ float Bs[2][SBK][SBN + SPAD];      // 68-float rows (16B aligned)

    const int tid = threadIdx.x;
    const int n0 = blockIdx.x * SBN;
    const int m0 = blockIdx.y * SBM;

    const int rg = tid >> 4;   // 0..15 : row-pair group
    const int cg = tid & 15;   // 0..15 : col quad

    // ---- global load indexing ----
    // A tile: 32 rows x 32 k -> 1 float4 per thread
    const int a_row = tid >> 3;          // 0..31
    const int a_kc  = (tid & 7) << 2;    // 0,4,...,28
    // B tile: 32 k x 64 n -> 2 float4 per thread
    const int b_kr0 = tid >> 4;          // 0..15 (i=0), +16 for i=1
    const int b_nc  = (tid & 15) << 2;   // 0,4,...,60

    float4 ar, br0, br1;

    auto loadG = [&](int kt) {
        ar  = *reinterpret_cast<const float4*>(
                  &A[(size_t)(m0 + a_row) * DH + kt * SBK + a_kc]);
        br0 = *reinterpret_cast<const float4*>(
                  &Bm[(size_t)(kt * SBK + b_kr0) * DH + n0 + b_nc]);
        br1 = *reinterpret_cast<const float4*>(
                  &Bm[(size_t)(kt * SBK + b_kr0 + 16) * DH + n0 + b_nc]);
    };
    auto storeS = [&](int p) {
        const int pos = ((a_row >> 1) << 2) + ((a_row & 1) << 1);
        float v[4] = {ar.x, ar.y, ar.z, ar.w};
#pragma unroll
        for (int j = 0; j < 4; j++) {
            As[p][a_kc + j][pos]     = v[j];
            As[p][a_kc + j][pos + 1] = v[j];
        }
        *reinterpret_cast<float4*>(&Bs[p][b_kr0][b_nc])      = br0;
        *reinterpret_cast<float4*>(&Bs[p][b_kr0 + 16][b_nc]) = br1;
    };

    unsigned long long acc00 = 0, acc01 = 0, acc10 = 0, acc11 = 0;

    const int nk = DH / SBK;  // 32
    loadG(0);
    storeS(0);
    __syncthreads();

    int p = 0;
    for (int kt = 0; kt < nk; kt++) {
        if (kt + 1 < nk) loadG(kt + 1);
#pragma unroll
        for (int k = 0; k < SBK; k++) {
            U64x2 a = *reinterpret_cast<const U64x2*>(&As[p][k][rg << 2]);
            U64x2 b = *reinterpret_cast<const U64x2*>(&Bs[p][k][cg << 2]);
            fma2(acc00, a.x, b.x);
            fma2(acc01, a.x, b.y);
            fma2(acc10, a.y, b.x);
            fma2(acc11, a.y, b.y);
        }
        if (kt + 1 < nk) {
            storeS(p ^ 1);
            __syncthreads();
            p ^= 1;
        }
    }

    // epilogue: tanh(acc + Z)
    const int row = m0 + (rg << 1);
    const int col = n0 + (cg << 2);
    {
        float2 p0 = unpack2(acc00);
        float2 p1 = unpack2(acc01);
        const size_t off = (size_t)row * DH + col;
        float4 z = *reinterpret_cast<const float4*>(&Z[off]);
        float4 v;
        v.x = tanhf(p0.x + z.x);
        v.y = tanhf(p0.y + z.y);
        v.z = tanhf(p1.x + z.z);
        v.w = tanhf(p1.y + z.w);
        *reinterpret_cast<float4*>(&C[off]) = v;
    }
    {
        float2 p0 = unpack2(acc10);
        float2 p1 = unpack2(acc11);
        const size_t off = (size_t)(row + 1) * DH + col;
        float4 z = *reinterpret_cast<const float4*>(&Z[off]);
        float4 v;
        v.x = tanhf(p0.x + z.x);
        v.y = tanhf(p0.y + z.y);
        v.z = tanhf(p1.x + z.z);
        v.w = tanhf(p1.y + z.w);
        *reinterpret_cast<float4*>(&C[off]) = v;
    }
}

// ---------------- generic tiled fp32x2 GEMM (precompute + readout) ----
// MODE 0: C = A@B + bias_vec[n]
// MODE 2: C = A@B + aux[0]
template <int BM, int BN, int BK, int TM, int MODE>
__global__ void __launch_bounds__(256)
gemm_f32x2(const float* __restrict__ A, const float* __restrict__ Bm,
           const float* __restrict__ aux, float* __restrict__ C,
           int M, int N, int K) {
    constexpr int TN = 4;
    constexpr int NT = (BM / TM) * (BN / TN);
    static_assert(NT == 256, "block must be 256 threads");
    constexpr int PADA = 4;

    __shared__ float As[BK][BM + PADA];
    __shared__ float Bs[BK][BN];

    const int tid = threadIdx.x;
    const int n0 = blockIdx.x * BN;
    const int m0 = blockIdx.y * BM;

    constexpr int A_PER = (BM * BK / 4) / NT;
    constexpr int B_PER = (BK * BN / 4) / NT;

    float4 ar[A_PER], br[B_PER];

    auto loadA = [&](int kt) {
#pragma unroll
        for (int i = 0; i < A_PER; i++) {
            int idx = tid + i * NT;
            int row = idx / (BK / 4);
            int kc  = idx % (BK / 4);
            ar[i] = *reinterpret_cast<const float4*>(
                &A[(size_t)(m0 + row) * K + kt * BK + kc * 4]);
        }
    };
    auto storeA = [&]() {
#pragma unroll
        for (int i = 0; i < A_PER; i++) {
            int idx = tid + i * NT;
            int row = idx / (BK / 4);
            int kc  = idx % (BK / 4);
            As[kc * 4 + 0][row] = ar[i].x;
            As[kc * 4 + 1][row] = ar[i].y;
            As[kc * 4 + 2][row] = ar[i].z;
            As[kc * 4 + 3][row] = ar[i].w;
        }
    };
    auto loadB = [&](int kt) {
#pragma unroll
        for (int i = 0; i < B_PER; i++) {
            int idx = tid + i * NT;
            int kr = idx / (BN / 4);
            int nc = idx % (BN / 4);
            br[i] = *reinterpret_cast<const float4*>(
                &Bm[(size_t)(kt * BK + kr) * N + n0 + nc * 4]);
        }
    };
    auto storeB = [&]() {
#pragma unroll
        for (int i = 0; i < B_PER; i++) {
            int idx = tid + i * NT;
            int kr = idx / (BN / 4);
            int nc = idx % (BN / 4);
            *reinterpret_cast<float4*>(&Bs[kr][nc * 4]) = br[i];
        }
    };

    unsigned long long acc[TM][2];
#pragma unroll
    for (int i = 0; i < TM; i++) {
        acc[i][0] = pack2(0.0f, 0.0f);
        acc[i][1] = pack2(0.0f, 0.0f);
    }

    const int rg = tid / (BN / TN);
    const int cg = tid % (BN / TN);
    const int r0 = rg * TM;
    const int c0 = cg * TN;

    const int nk = K / BK;
    loadA(0); loadB(0);
    storeA(); storeB();
    __syncthreads();

    for (int kt = 0; kt < nk; kt++) {
        if (kt + 1 < nk) { loadA(kt + 1); loadB(kt + 1); }
#pragma unroll
        for (int k = 0; k < BK; k++) {
            float a[TM];
            if (TM == 2) {
                float2 av = *reinterpret_cast<const float2*>(&As[k][r0]);
                a[0] = av.x; a[1] = av.y;
            } else {
                float4 av = *reinterpret_cast<const float4*>(&As[k][r0]);
                a[0] = av.x; a[1] = av.y; a[2] = av.z; a[3] = av.w;
            }
            float4 bv = *reinterpret_cast<const float4*>(&Bs[k][c0]);
            unsigned long long b01 = pack2(bv.x, bv.y);
            unsigned long long b23 = pack2(bv.z, bv.w);
#pragma unroll
            for (int i = 0; i < TM; i++) {
                unsigned long long aa = pack2(a[i], a[i]);
                fma2(acc[i][0], aa, b01);
                fma2(acc[i][1], aa, b23);
            }
        }
        __syncthreads();
        if (kt + 1 < nk) { storeA(); storeB(); __syncthreads(); }
    }

#pragma unroll
    for (int i = 0; i < TM; i++) {
        float2 p0 = unpack2(acc[i][0]);
        float2 p1 = unpack2(acc[i][1]);
        float4 v = make_float4(p0.x, p0.y, p1.x, p1.y);
        const int row = m0 + r0 + i;
        const int col = n0 + c0;
        const size_t off = (size_t)row * N + col;
        if (MODE == 0) {
            float4 b = *reinterpret_cast<const float4*>(&aux[col]);
            v.x += b.x; v.y += b.y; v.z += b.z; v.w += b.w;
        } else {
            float s = aux[0];
            v.x += s; v.y += s; v.z += s; v.w += s;
        }
        *reinterpret_cast<float4*>(&C[off]) = v;
    }
}

extern "C" void kernel_launch(void* const* d_in, const int* in_sizes, int n_in,
                              void* d_out, int out_size) {
    const float* xs  = (const float*)d_in[0];  // [128,256,256]
    const float* W1x = (const float*)d_in[1];  // [256,1024]
    const float* W1h = (const float*)d_in[2];  // [1024,1024]
    const float* b1  = (const float*)d_in[3];  // [1024]
    const float* W2  = (const float*)d_in[4];  // [1024,256]
    const float* b2  = (const float*)d_in[5];  // scalar
    float* out = (float*)d_out;                // [256,256]

    float* zp = nullptr;
    float* hp = nullptr;
    cudaGetSymbolAddress((void**)&zp, g_z);
    cudaGetSymbolAddress((void**)&hp, g_h);
    float* h0 = hp;
    float* h1 = hp + (size_t)BATCH * DH;

    // h(-1) = 0
    {
        int n = BATCH * DH;
        zero_kernel<<<(n + 255) / 256, 256>>>(h0, n);
    }

    // Z[t,b,:] = xs[t,b,:] @ W1x + b1   (M = T*B = 32768, N = 1024, K = 256)
    gemm_f32x2<64, 64, 32, 4, 0>
        <<<dim3(DH / 64, (T_STEPS * BATCH) / 64), 256>>>(
            xs, W1x, b1, zp, T_STEPS * BATCH, DH, DIN);

    // Recurrence: h <- tanh(Z[t] + h @ W1h)
    for (int t = 0; t < T_STEPS; t++) {
        float* hc = (t & 1) ? h1 : h0;
        float* hn = (t & 1) ? h0 : h1;
        step_kernel<<<dim3(DH / SBN, BATCH / SBM), 256>>>(
            hc, W1h, zp + (size_t)t * BATCH * DH, hn);
    }

    // out = h_final @ W2 + b2
    gemm_f32x2<32, 64, 32, 2, 2>
        <<<dim3(DOUT / 64, BATCH / 32), 256>>>(
            h0, W2, b2, out, BATCH, DOUT, DH);
}

// round 4
// speedup vs baseline: 3.1279x; 3.1279x over previous
#include <cuda_runtime.h>
#include <cuda_bf16.h>
#include <math.h>
#include <stdint.h>

#define T_STEPS 128
#define BATCH   256
#define DIN     256
#define DH      1024
#define DOUT    256

// ---------------- device scratch ----------------
__device__ float g_z[(size_t)T_STEPS * BATCH * DH];          // 134 MB: xs@W1x + b1
__device__ float g_hf[(size_t)BATCH * DH];                   // fp32 h (for readout)
__device__ __nv_bfloat16 g_h_hi[2][(size_t)BATCH * DH];      // ping-pong split h
__device__ __nv_bfloat16 g_h_lo[2][(size_t)BATCH * DH];
__device__ __nv_bfloat16 g_wt_hi[(size_t)DH * DH];           // W1h^T split: wt[n][k] = W1h[k][n]
__device__ __nv_bfloat16 g_wt_lo[(size_t)DH * DH];

// ---------------- helpers ----------------
__device__ __forceinline__ uint32_t smem_u32(const void* p) {
    uint32_t a;
    asm("{ .reg .u64 t; cvta.to.shared.u64 t, %1; cvt.u32.u64 %0, t; }" : "=r"(a) : "l"(p));
    return a;
}
__device__ __forceinline__ void cp_async16(uint32_t dst, const void* src) {
    asm volatile("cp.async.cg.shared.global [%0], [%1], 16;" :: "r"(dst), "l"(src) : "memory");
}
__device__ __forceinline__ void cp_commit() {
    asm volatile("cp.async.commit_group;" ::: "memory");
}
__device__ __forceinline__ void cp_wait1() {
    asm volatile("cp.async.wait_group 1;" ::: "memory");
}
__device__ __forceinline__ void ldmatrix_x4(uint32_t& r0, uint32_t& r1,
                                            uint32_t& r2, uint32_t& r3, uint32_t addr) {
    asm volatile("ldmatrix.sync.aligned.m8n8.x4.shared.b16 {%0,%1,%2,%3}, [%4];"
                 : "=r"(r0), "=r"(r1), "=r"(r2), "=r"(r3) : "r"(addr));
}
__device__ __forceinline__ void mma_bf16(float* c, uint32_t a0, uint32_t a1,
                                         uint32_t a2, uint32_t a3,
                                         uint32_t b0, uint32_t b1) {
    asm volatile(
        "mma.sync.aligned.m16n8k16.row.col.f32.bf16.bf16.f32 "
        "{%0,%1,%2,%3},{%4,%5,%6,%7},{%8,%9},{%0,%1,%2,%3};"
        : "+f"(c[0]), "+f"(c[1]), "+f"(c[2]), "+f"(c[3])
        : "r"(a0), "r"(a1), "r"(a2), "r"(a3), "r"(b0), "r"(b1));
}
__device__ __forceinline__ float tanh_fast(float x) {
    float ax = fabsf(x);
    float e;
    asm("ex2.approx.f32 %0, %1;" : "=f"(e) : "f"(ax * -2.885390081777927f)); // e^{-2|x|}
    float r = __fdividef(1.0f - e, 1.0f + e);
    return __uint_as_float(__float_as_uint(r) | (__float_as_uint(x) & 0x80000000u));
}
__device__ __forceinline__ uint32_t prmt_hi(uint32_t x, uint32_t y) {
    uint32_t d;
    asm("prmt.b32 %0, %1, %2, 0x7632;" : "=r"(d) : "r"(x), "r"(y));
    return d;
}
__device__ __forceinline__ uint32_t cvt_bf16x2(float hi, float lo) {
    uint32_t d;  // d.hi16 = cvt(hi), d.lo16 = cvt(lo)
    asm("cvt.rn.bf16x2.f32 %0, %1, %2;" : "=r"(d) : "f"(hi), "f"(lo));
    return d;
}

// ---------------- utility kernels ----------------
__global__ void zero_u4(uint4* __restrict__ p, int n4) {
    int i = blockIdx.x * blockDim.x + threadIdx.x;
    if (i < n4) p[i] = make_uint4(0, 0, 0, 0);
}

// transpose + bf16 split of W1h: wt[n][k] = split(W1h[k][n])
__global__ void wsplit_kernel(const float* __restrict__ W,
                              __nv_bfloat16* __restrict__ hi,
                              __nv_bfloat16* __restrict__ lo) {
    __shared__ float t[32][33];
    const int tx = threadIdx.x, ty = threadIdx.y;
    const int kb = blockIdx.y * 32, nb = blockIdx.x * 32;
#pragma unroll
    for (int i = 0; i < 32; i += 8)
        t[ty + i][tx] = W[(size_t)(kb + ty + i) * DH + nb + tx];
    __syncthreads();
#pragma unroll
    for (int i = 0; i < 32; i += 8) {
        const int n = nb + ty + i, k = kb + tx;
        float v = t[tx][ty + i];
        __nv_bfloat16 h = __float2bfloat16(v);
        hi[(size_t)n * DH + k] = h;
        lo[(size_t)n * DH + k] = __float2bfloat16(v - __bfloat162float(h));
    }
}

// =====================================================================
// HMMA step kernel: H_next = tanh(Z + H @ W1h), fp32 via bf16 3-term.
// grid (16, 8): n0 = bx*64, m0 = by*32.  128 threads (4 warps).
// Warp w covers n columns [w*16, w*16+16), all 32 m rows.
// K = 48 tiles of 64: seg0 (h_hi,wt_hi), seg1 (h_lo,wt_hi), seg2 (h_hi,wt_lo).
// =====================================================================
__global__ void __launch_bounds__(128, 1)
step_hmma(const __nv_bfloat16* __restrict__ h_hi, const __nv_bfloat16* __restrict__ h_lo,
          const __nv_bfloat16* __restrict__ wt_hi, const __nv_bfloat16* __restrict__ wt_lo,
          const float* __restrict__ Zt,
          __nv_bfloat16* __restrict__ o_hi, __nv_bfloat16* __restrict__ o_lo,
          float* __restrict__ o_f) {
    __shared__ __align__(128) char sAbuf[3][32 * 128];  // 4 KB  / buffer
    __shared__ __align__(128) char sBbuf[3][64 * 128];  // 8 KB / buffer

    const int tid = threadIdx.x;
    const int w = tid >> 5;
    const int lane = tid & 31;
    const int n0 = blockIdx.x * 64;
    const int m0 = blockIdx.y * 32;

    // ---- producer: cp.async one 48-element... one 64-k tile ----
    auto issue = [&](int kt, int buf) {
        const int seg = kt >> 4;
        const int k0 = (kt & 15) << 6;  // element offset within DH
        const __nv_bfloat16* Ap = (seg == 1) ? h_lo : h_hi;
        const __nv_bfloat16* Bp = (seg == 2) ? wt_lo : wt_hi;
        const uint32_t sA = smem_u32(sAbuf[buf]);
        const uint32_t sB = smem_u32(sBbuf[buf]);
#pragma unroll
        for (int i = 0; i < 2; i++) {           // A: 32 rows x 128B = 256 chunks
            const int c = tid + (i << 7);
            const int row = c >> 3, kb = (c & 7) << 4;
            const uint32_t dst = sA + row * 128 + (kb ^ ((row & 7) << 4));
            cp_async16(dst, (const char*)(Ap + (size_t)(m0 + row) * DH + k0) + kb);
        }
#pragma unroll
        for (int i = 0; i < 4; i++) {           // B: 64 rows x 128B = 512 chunks
            const int c = tid + (i << 7);
            const int row = c >> 3, kb = (c & 7) << 4;
            const uint32_t dst = sB + row * 128 + (kb ^ ((row & 7) << 4));
            cp_async16(dst, (const char*)(Bp + (size_t)(n0 + row) * DH + k0) + kb);
        }
    };

    // ---- consumer per-lane ldmatrix addressing ----
    const int l7 = lane & 7;
    const uint32_t xmk = (uint32_t)(l7 << 4);
    const int rowAq = ((lane >> 3) & 1) * 8 + l7;       // + mt*16
    const uint32_t kselA = ((lane >> 4) & 1) * 16;
    const int rowB = w * 16 + ((lane >> 4) & 1) * 8 + l7;
    const uint32_t kselB = ((lane >> 3) & 1) * 16;

    float acc[2][2][4];
#pragma unroll
    for (int mt = 0; mt < 2; mt++)
#pragma unroll
        for (int nt = 0; nt < 2; nt++)
#pragma unroll
            for (int q = 0; q < 4; q++) acc[mt][nt][q] = 0.0f;

    auto compute = [&](int buf) {
        const uint32_t sA = smem_u32(sAbuf[buf]);
        const uint32_t sB = smem_u32(sBbuf[buf]);
#pragma unroll
        for (int k16 = 0; k16 < 4; k16++) {
            uint32_t b00, b01, b10, b11;
            ldmatrix_x4(b00, b01, b10, b11,
                        sB + rowB * 128 + (((uint32_t)(k16 * 32) + kselB) ^ xmk));
#pragma unroll
            for (int mt = 0; mt < 2; mt++) {
                uint32_t a0, a1, a2, a3;
                ldmatrix_x4(a0, a1, a2, a3,
                            sA + (mt * 16 + rowAq) * 128 +
                                (((uint32_t)(k16 * 32) + kselA) ^ xmk));
                mma_bf16(acc[mt][0], a0, a1, a2, a3, b00, b01);
                mma_bf16(acc[mt][1], a0, a1, a2, a3, b10, b11);
            }
        }
    };

    // ---- pipeline: 3 buffers, depth 2 ----
    issue(0, 0); cp_commit();
    issue(1, 1); cp_commit();
    for (int kt = 0; kt < 48; kt++) {
        cp_wait1();
        __syncthreads();
        if (kt + 2 < 48) issue(kt + 2, (kt + 2) % 3);
        cp_commit();
        compute(kt % 3);
    }

    // ---- epilogue: tanh(acc + Z), write f32 + hi/lo bf16 ----
    const int g = lane >> 2, t4 = lane & 3;
#pragma unroll
    for (int mt = 0; mt < 2; mt++) {
#pragma unroll
        for (int nt = 0; nt < 2; nt++) {
            const float* c = acc[mt][nt];
            const int col = n0 + w * 16 + nt * 8 + 2 * t4;
            const int r0 = m0 + mt * 16 + g;
            const size_t o0 = (size_t)r0 * DH + col;
            const size_t o1 = o0 + 8 * DH;
            float2 z0 = *reinterpret_cast<const float2*>(Zt + o0);
            float2 z1 = *reinterpret_cast<const float2*>(Zt + o1);
            float v0 = tanh_fast(c[0] + z0.x);
            float v1 = tanh_fast(c[1] + z0.y);
            float v2 = tanh_fast(c[2] + z1.x);
            float v3 = tanh_fast(c[3] + z1.y);
            *reinterpret_cast<float2*>(o_f + o0) = make_float2(v0, v1);
            *reinterpret_cast<float2*>(o_f + o1) = make_float2(v2, v3);
            // rz hi/lo split
            uint32_t u0 = __float_as_uint(v0), u1 = __float_as_uint(v1);
            uint32_t u2 = __float_as_uint(v2), u3 = __float_as_uint(v3);
            *reinterpret_cast<uint32_t*>(o_hi + o0) = prmt_hi(u0, u1);
            *reinterpret_cast<uint32_t*>(o_hi + o1) = prmt_hi(u2, u3);
            float l0 = v0 - __uint_as_float(u0 & 0xFFFF0000u);
            float l1 = v1 - __uint_as_float(u1 & 0xFFFF0000u);
            float l2 = v2 - __uint_as_float(u2 & 0xFFFF0000u);
            float l3 = v3 - __uint_as_float(u3 & 0xFFFF0000u);
            *reinterpret_cast<uint32_t*>(o_lo + o0) = cvt_bf16x2(l1, l0);
            *reinterpret_cast<uint32_t*>(o_lo + o1) = cvt_bf16x2(l3, l2);
        }
    }
}

// ---------------- packed f32x2 GEMM (precompute + readout) ----------------
__device__ __forceinline__ void fma2(unsigned long long& acc,
                                     unsigned long long a, unsigned long long b) {
    asm("fma.rn.f32x2 %0, %1, %2, %0;" : "+l"(acc) : "l"(a), "l"(b));
}
__device__ __forceinline__ unsigned long long pack2(float x, float y) {
    unsigned long long r;
    asm("mov.b64 %0, {%1, %2};" : "=l"(r) : "f"(x), "f"(y));
    return r;
}
__device__ __forceinline__ float2 unpack2(unsigned long long v) {
    float2 f;
    asm("mov.b64 {%0, %1}, %2;" : "=f"(f.x), "=f"(f.y) : "l"(v));
    return f;
}

// MODE 0: C = A@B + bias_vec[n]    MODE 2: C = A@B + aux[0]
template <int BM, int BN, int BK, int TM, int MODE>
__global__ void __launch_bounds__(256)
gemm_f32x2(const float* __restrict__ A, const float* __restrict__ Bm,
           const float* __restrict__ aux, float* __restrict__ C,
           int M, int N, int K) {
    constexpr int TN = 4;
    constexpr int NT = (BM / TM) * (BN / TN);
    static_assert(NT == 256, "block must be 256 threads");
    __shared__ float As[BK][BM + 4];
    __shared__ float Bs[BK][BN];

    const int tid = threadIdx.x;
    const int n0 = blockIdx.x * BN;
    const int m0 = blockIdx.y * BM;
    constexpr int A_PER = (BM * BK / 4) / NT;
    constexpr int B_PER = (BK * BN / 4) / NT;
    float4 ar[A_PER], br[B_PER];

    auto loadA = [&](int kt) {
#pragma unroll
        for (int i = 0; i < A_PER; i++) {
            int idx = tid + i * NT, row = idx / (BK / 4), kc = idx % (BK / 4);
            ar[i] = *reinterpret_cast<const float4*>(&A[(size_t)(m0 + row) * K + kt * BK + kc * 4]);
        }
    };
    auto storeA = [&]() {
#pragma unroll
        for (int i = 0; i < A_PER; i++) {
            int idx = tid + i * NT, row = idx / (BK / 4), kc = idx % (BK / 4);
            As[kc * 4 + 0][row] = ar[i].x; As[kc * 4 + 1][row] = ar[i].y;
            As[kc * 4 + 2][row] = ar[i].z; As[kc * 4 + 3][row] = ar[i].w;
        }
    };
    auto loadB = [&](int kt) {
#pragma unroll
        for (int i = 0; i < B_PER; i++) {
            int idx = tid + i * NT, kr = idx / (BN / 4), nc = idx % (BN / 4);
            br[i] = *reinterpret_cast<const float4*>(&Bm[(size_t)(kt * BK + kr) * N + n0 + nc * 4]);
        }
    };
    auto storeB = [&]() {
#pragma unroll
        for (int i = 0; i < B_PER; i++) {
            int idx = tid + i * NT, kr = idx / (BN / 4), nc = idx % (BN / 4);
            *reinterpret_cast<float4*>(&Bs[kr][nc * 4]) = br[i];
        }
    };

    unsigned long long acc[TM][2];
#pragma unroll
    for (int i = 0; i < TM; i++) { acc[i][0] = pack2(0, 0); acc[i][1] = pack2(0, 0); }

    const int rg = tid / (BN / TN), cg = tid % (BN / TN);
    const int r0 = rg * TM, c0 = cg * TN;
    const int nk = K / BK;
    loadA(0); loadB(0); storeA(); storeB();
    __syncthreads();
    for (int kt = 0; kt < nk; kt++) {
        if (kt + 1 < nk) { loadA(kt + 1); loadB(kt + 1); }
#pragma unroll
        for (int k = 0; k < BK; k++) {
            float a[TM];
            if (TM == 2) {
                float2 avv = *reinterpret_cast<const float2*>(&As[k][r0]);
                a[0] = avv.x; a[1] = avv.y;
            } else {
                float4 avv = *reinterpret_cast<const float4*>(&As[k][r0]);
                a[0] = avv.x; a[1] = avv.y; a[2] = avv.z; a[3] = avv.w;
            }
            float4 bvv = *reinterpret_cast<const float4*>(&Bs[k][c0]);
            unsigned long long b01 = pack2(bvv.x, bvv.y), b23 = pack2(bvv.z, bvv.w);
#pragma unroll
            for (int i = 0; i < TM; i++) {
                unsigned long long aa = pack2(a[i], a[i]);
                fma2(acc[i][0], aa, b01);
                fma2(acc[i][1], aa, b23);
            }
        }
        __syncthreads();
        if (kt + 1 < nk) { storeA(); storeB(); __syncthreads(); }
    }
#pragma unroll
    for (int i = 0; i < TM; i++) {
        float2 p0 = unpack2(acc[i][0]), p1 = unpack2(acc[i][1]);
        float4 v = make_float4(p0.x, p0.y, p1.x, p1.y);
        const int row = m0 + r0 + i, col = n0 + c0;
        const size_t off = (size_t)row * N + col;
        if (MODE == 0) {
            float4 b = *reinterpret_cast<const float4*>(&aux[col]);
            v.x += b.x; v.y += b.y; v.z += b.z; v.w += b.w;
        } else {
            float s = aux[0];
            v.x += s; v.y += s; v.z += s; v.w += s;
        }
        *reinterpret_cast<float4*>(&C[off]) = v;
    }
}

// ---------------- host launcher ----------------
extern "C" void kernel_launch(void* const* d_in, const int* in_sizes, int n_in,
                              void* d_out, int out_size) {
    const float* xs  = (const float*)d_in[0];
    const float* W1x = (const float*)d_in[1];
    const float* W1h = (const float*)d_in[2];
    const float* b1  = (const float*)d_in[3];
    const float* W2  = (const float*)d_in[4];
    const float* b2  = (const float*)d_in[5];
    float* out = (float*)d_out;

    float *zp, *hf;
    __nv_bfloat16 *hhi, *hlo, *wthi, *wtlo;
    cudaGetSymbolAddress((void**)&zp, g_z);
    cudaGetSymbolAddress((void**)&hf, g_hf);
    cudaGetSymbolAddress((void**)&hhi, g_h_hi);
    cudaGetSymbolAddress((void**)&hlo, g_h_lo);
    cudaGetSymbolAddress((void**)&wthi, g_wt_hi);
    cudaGetSymbolAddress((void**)&wtlo, g_wt_lo);

    const size_t HS = (size_t)BATCH * DH;

    // zero h ping-pong buffer 0 (hi + lo): HS bf16 = HS*2 bytes = HS/8 uint4
    zero_u4<<<(int)(HS / 8 / 256), 256>>>((uint4*)hhi, (int)(HS / 8));
    zero_u4<<<(int)(HS / 8 / 256), 256>>>((uint4*)hlo, (int)(HS / 8));

    // W1h^T bf16 split
    wsplit_kernel<<<dim3(32, 32), dim3(32, 8)>>>(W1h, wthi, wtlo);

    // Z = xs@W1x + b1
    gemm_f32x2<64, 64, 32, 4, 0>
        <<<dim3(DH / 64, (T_STEPS * BATCH) / 64), 256>>>(
            xs, W1x, b1, zp, T_STEPS * BATCH, DH, DIN);

    // recurrence
    for (int t = 0; t < T_STEPS; t++) {
        const int cur = t & 1, nxt = cur ^ 1;
        step_hmma<<<dim3(16, 8), 128>>>(
            hhi + cur * HS, hlo + cur * HS, wthi, wtlo,
            zp + (size_t)t * HS,
            hhi + nxt * HS, hlo + nxt * HS, hf);
    }

    // out = h_final @ W2 + b2
    gemm_f32x2<32, 64, 32, 2, 2>
        <<<dim3(DOUT / 64, BATCH / 32), 256>>>(hf, W2, b2, out, BATCH, DOUT, DH);
}

// round 5
// speedup vs baseline: 4.0988x; 1.3104x over previous
#include <cuda_runtime.h>
#include <cuda_bf16.h>
#include <math.h>
#include <stdint.h>

#define T_STEPS 128
#define BATCH   256
#define DIN     256
#define DH      1024
#define DOUT    256

// ---------------- device scratch ----------------
__device__ float g_z[(size_t)T_STEPS * BATCH * DH];          // 134 MB: xs@W1x + b1
__device__ float g_hf[(size_t)BATCH * DH];                   // fp32 h (final step only)
__device__ __nv_bfloat16 g_h_hi[2][(size_t)BATCH * DH];      // ping-pong split h
__device__ __nv_bfloat16 g_h_lo[2][(size_t)BATCH * DH];
__device__ __nv_bfloat16 g_wt_hi[(size_t)DH * DH];           // W1h^T split: wt[n][k]
__device__ __nv_bfloat16 g_wt_lo[(size_t)DH * DH];
__device__ __nv_bfloat16 g_xs_hi[(size_t)T_STEPS * BATCH * DIN];  // xs split
__device__ __nv_bfloat16 g_xs_lo[(size_t)T_STEPS * BATCH * DIN];
__device__ __nv_bfloat16 g_w1xt_hi[(size_t)DH * DIN];        // W1x^T split: [n=1024][k=256]
__device__ __nv_bfloat16 g_w1xt_lo[(size_t)DH * DIN];

// ---------------- helpers ----------------
__device__ __forceinline__ uint32_t smem_u32(const void* p) {
    uint32_t a;
    asm("{ .reg .u64 t; cvta.to.shared.u64 t, %1; cvt.u32.u64 %0, t; }" : "=r"(a) : "l"(p));
    return a;
}
__device__ __forceinline__ void cp_async16(uint32_t dst, const void* src) {
    asm volatile("cp.async.cg.shared.global [%0], [%1], 16;" :: "r"(dst), "l"(src) : "memory");
}
__device__ __forceinline__ void cp_commit() {
    asm volatile("cp.async.commit_group;" ::: "memory");
}
__device__ __forceinline__ void cp_wait1() {
    asm volatile("cp.async.wait_group 1;" ::: "memory");
}
__device__ __forceinline__ void cp_wait0() {
    asm volatile("cp.async.wait_group 0;" ::: "memory");
}
__device__ __forceinline__ void ldmatrix_x4(uint32_t& r0, uint32_t& r1,
                                            uint32_t& r2, uint32_t& r3, uint32_t addr) {
    asm volatile("ldmatrix.sync.aligned.m8n8.x4.shared.b16 {%0,%1,%2,%3}, [%4];"
                 : "=r"(r0), "=r"(r1), "=r"(r2), "=r"(r3) : "r"(addr));
}
__device__ __forceinline__ void mma_bf16(float* c, uint32_t a0, uint32_t a1,
                                         uint32_t a2, uint32_t a3,
                                         uint32_t b0, uint32_t b1) {
    asm volatile(
        "mma.sync.aligned.m16n8k16.row.col.f32.bf16.bf16.f32 "
        "{%0,%1,%2,%3},{%4,%5,%6,%7},{%8,%9},{%0,%1,%2,%3};"
        : "+f"(c[0]), "+f"(c[1]), "+f"(c[2]), "+f"(c[3])
        : "r"(a0), "r"(a1), "r"(a2), "r"(a3), "r"(b0), "r"(b1));
}
__device__ __forceinline__ float tanh_fast(float x) {
    float ax = fabsf(x);
    float e;
    asm("ex2.approx.f32 %0, %1;" : "=f"(e) : "f"(ax * -2.885390081777927f)); // e^{-2|x|}
    float r = __fdividef(1.0f - e, 1.0f + e);
    return __uint_as_float(__float_as_uint(r) | (__float_as_uint(x) & 0x80000000u));
}
__device__ __forceinline__ uint32_t prmt_hi(uint32_t x, uint32_t y) {
    uint32_t d;  // d = [hi16(x), hi16(y)] in element order
    asm("prmt.b32 %0, %1, %2, 0x7632;" : "=r"(d) : "r"(x), "r"(y));
    return d;
}
__device__ __forceinline__ uint32_t cvt_bf16x2(float hi, float lo) {
    uint32_t d;  // element order [lo, hi]
    asm("cvt.rn.bf16x2.f32 %0, %1, %2;" : "=r"(d) : "f"(hi), "f"(lo));
    return d;
}

// ---------------- utility kernels ----------------
__global__ void zero_u4(uint4* __restrict__ p, int n4) {
    int i = blockIdx.x * blockDim.x + threadIdx.x;
    if (i < n4) p[i] = make_uint4(0, 0, 0, 0);
}

// elementwise fp32 -> bf16 hi/lo split (vectorized by 4)
__global__ void fsplit_kernel(const float* __restrict__ in,
                              __nv_bfloat16* __restrict__ hi,
                              __nv_bfloat16* __restrict__ lo, int n4) {
    int i = blockIdx.x * blockDim.x + threadIdx.x;
    if (i >= n4) return;
    float4 v = reinterpret_cast<const float4*>(in)[i];
    uint32_t u0 = __float_as_uint(v.x), u1 = __float_as_uint(v.y);
    uint32_t u2 = __float_as_uint(v.z), u3 = __float_as_uint(v.w);
    reinterpret_cast<uint2*>(hi)[i] = make_uint2(prmt_hi(u0, u1), prmt_hi(u2, u3));
    float l0 = v.x - __uint_as_float(u0 & 0xFFFF0000u);
    float l1 = v.y - __uint_as_float(u1 & 0xFFFF0000u);
    float l2 = v.z - __uint_as_float(u2 & 0xFFFF0000u);
    float l3 = v.w - __uint_as_float(u3 & 0xFFFF0000u);
    reinterpret_cast<uint2*>(lo)[i] = make_uint2(cvt_bf16x2(l1, l0), cvt_bf16x2(l3, l2));
}

// transpose + bf16 split: W[k][n] (KxN) -> out[n][k]
__global__ void wsplit_kernel(const float* __restrict__ W,
                              __nv_bfloat16* __restrict__ hi,
                              __nv_bfloat16* __restrict__ lo, int K, int N) {
    __shared__ float t[32][33];
    const int tx = threadIdx.x, ty = threadIdx.y;
    const int kb = blockIdx.y * 32, nb = blockIdx.x * 32;
#pragma unroll
    for (int i = 0; i < 32; i += 8)
        t[ty + i][tx] = W[(size_t)(kb + ty + i) * N + nb + tx];
    __syncthreads();
#pragma unroll
    for (int i = 0; i < 32; i += 8) {
        const int n = nb + ty + i, k = kb + tx;
        float v = t[tx][ty + i];
        __nv_bfloat16 h = __float2bfloat16(v);
        hi[(size_t)n * K + k] = h;
        lo[(size_t)n * K + k] = __float2bfloat16(v - __bfloat162float(h));
    }
}

// =====================================================================
// Step kernel v2 (split-K across warps):
// H_next = tanh(Z + H @ W1h), fp32 via bf16 3-term, K = 48 tiles of 64.
// grid (16, 8), 128 threads. CTA tile 32(M) x 64(N).
// Warp w computes the FULL 32x64 output for k16-slice w of each tile;
// 4 partials reduced through smem at the end, fused with tanh epilogue.
// =====================================================================
__global__ void __launch_bounds__(128, 1)
step_hmma(const __nv_bfloat16* __restrict__ h_hi, const __nv_bfloat16* __restrict__ h_lo,
          const __nv_bfloat16* __restrict__ wt_hi, const __nv_bfloat16* __restrict__ wt_lo,
          const float* __restrict__ Zt,
          __nv_bfloat16* __restrict__ o_hi, __nv_bfloat16* __restrict__ o_lo,
          float* __restrict__ o_f) {
    __shared__ __align__(128) char pool[36864];  // 3x(4KB A + 8KB B); reused for reduction

    const int tid = threadIdx.x;
    const int w = tid >> 5;
    const int lane = tid & 31;
    const int n0 = blockIdx.x * 64;
    const int m0 = blockIdx.y * 32;

    auto sA = [&](int buf) { return smem_u32(pool) + buf * 4096; };
    auto sB = [&](int buf) { return smem_u32(pool) + 12288 + buf * 8192; };

    auto issue = [&](int kt, int buf) {
        const int seg = kt >> 4;
        const int k0 = (kt & 15) << 6;
        const __nv_bfloat16* Ap = (seg == 1) ? h_lo : h_hi;
        const __nv_bfloat16* Bp = (seg == 2) ? wt_lo : wt_hi;
        const uint32_t a = sA(buf), b = sB(buf);
#pragma unroll
        for (int i = 0; i < 2; i++) {           // A: 32 rows x 128B
            const int c = tid + (i << 7);
            const int row = c >> 3, kb = (c & 7) << 4;
            cp_async16(a + row * 128 + (kb ^ ((row & 7) << 4)),
                       (const char*)(Ap + (size_t)(m0 + row) * DH + k0) + kb);
        }
#pragma unroll
        for (int i = 0; i < 4; i++) {           // B: 64 rows x 128B
            const int c = tid + (i << 7);
            const int row = c >> 3, kb = (c & 7) << 4;
            cp_async16(b + row * 128 + (kb ^ ((row & 7) << 4)),
                       (const char*)(Bp + (size_t)(n0 + row) * DH + k0) + kb);
        }
    };

    const int l7 = lane & 7;
    const uint32_t xmk = (uint32_t)(l7 << 4);
    const int rowA = ((lane >> 3) & 1) * 8 + l7;
    const uint32_t kselA = ((lane >> 4) & 1) * 16;
    const int rowBb = ((lane >> 4) & 1) * 8 + l7;
    const uint32_t kselB = ((lane >> 3) & 1) * 16;
    const uint32_t kbyte = (uint32_t)(w * 32);   // this warp's k16 slice

    float acc[2][8][4];
#pragma unroll
    for (int mt = 0; mt < 2; mt++)
#pragma unroll
        for (int n8 = 0; n8 < 8; n8++)
#pragma unroll
            for (int q = 0; q < 4; q++) acc[mt][n8][q] = 0.0f;

    auto compute = [&](int buf) {
        const uint32_t a = sA(buf), b = sB(buf);
        uint32_t af[2][4];
#pragma unroll
        for (int mt = 0; mt < 2; mt++)
            ldmatrix_x4(af[mt][0], af[mt][1], af[mt][2], af[mt][3],
                        a + (mt * 16 + rowA) * 128 + ((kbyte + kselA) ^ xmk));
#pragma unroll
        for (int nt = 0; nt < 4; nt++) {
            uint32_t b0, b1, b2, b3;
            ldmatrix_x4(b0, b1, b2, b3,
                        b + (nt * 16 + rowBb) * 128 + ((kbyte + kselB) ^ xmk));
#pragma unroll
            for (int mt = 0; mt < 2; mt++) {
                mma_bf16(acc[mt][nt * 2],     af[mt][0], af[mt][1], af[mt][2], af[mt][3], b0, b1);
                mma_bf16(acc[mt][nt * 2 + 1], af[mt][0], af[mt][1], af[mt][2], af[mt][3], b2, b3);
            }
        }
    };

    issue(0, 0); cp_commit();
    issue(1, 1); cp_commit();
    for (int kt = 0; kt < 48; kt++) {
        cp_wait1();
        __syncthreads();
        if (kt + 2 < 48) issue(kt + 2, (kt + 2) % 3);
        cp_commit();
        compute(kt % 3);
    }

    // ---- cross-warp reduction through smem (reuse pool) ----
    cp_wait0();
    __syncthreads();
    constexpr int RP = 68;  // padded row pitch (floats)
    float* sred = reinterpret_cast<float*>(pool);       // [4][32][68] = 34816B
    float* ms = sred + w * (32 * RP);
    const int g = lane >> 2, t4 = lane & 3;
#pragma unroll
    for (int mt = 0; mt < 2; mt++)
#pragma unroll
        for (int n8 = 0; n8 < 8; n8++) {
            const int r0 = mt * 16 + g, c = n8 * 8 + 2 * t4;
            *reinterpret_cast<float2*>(&ms[r0 * RP + c]) =
                make_float2(acc[mt][n8][0], acc[mt][n8][1]);
            *reinterpret_cast<float2*>(&ms[(r0 + 8) * RP + c]) =
                make_float2(acc[mt][n8][2], acc[mt][n8][3]);
        }
    __syncthreads();

    // ---- fused epilogue: sum 4 partials + Z, tanh, store splits ----
    const int row = tid >> 2;
    const int c0 = (tid & 3) * 16;
#pragma unroll
    for (int q = 0; q < 4; q++) {
        const int col = c0 + q * 4;
        float4 s = *reinterpret_cast<const float4*>(&sred[0 * 32 * RP + row * RP + col]);
#pragma unroll
        for (int w2 = 1; w2 < 4; w2++) {
            float4 p = *reinterpret_cast<const float4*>(&sred[w2 * 32 * RP + row * RP + col]);
            s.x += p.x; s.y += p.y; s.z += p.z; s.w += p.w;
        }
        const size_t off = (size_t)(m0 + row) * DH + n0 + col;
        float4 z = *reinterpret_cast<const float4*>(Zt + off);
        float v0 = tanh_fast(s.x + z.x);
        float v1 = tanh_fast(s.y + z.y);
        float v2 = tanh_fast(s.z + z.z);
        float v3 = tanh_fast(s.w + z.w);
        if (o_f) *reinterpret_cast<float4*>(o_f + off) = make_float4(v0, v1, v2, v3);
        uint32_t u0 = __float_as_uint(v0), u1 = __float_as_uint(v1);
        uint32_t u2 = __float_as_uint(v2), u3 = __float_as_uint(v3);
        *reinterpret_cast<uint2*>(o_hi + off) = make_uint2(prmt_hi(u0, u1), prmt_hi(u2, u3));
        float l0 = v0 - __uint_as_float(u0 & 0xFFFF0000u);
        float l1 = v1 - __uint_as_float(u1 & 0xFFFF0000u);
        float l2 = v2 - __uint_as_float(u2 & 0xFFFF0000u);
        float l3 = v3 - __uint_as_float(u3 & 0xFFFF0000u);
        *reinterpret_cast<uint2*>(o_lo + off) = make_uint2(cvt_bf16x2(l1, l0), cvt_bf16x2(l3, l2));
    }
}

// =====================================================================
// Precompute kernel: Z = xs @ W1x + b1, fp32 via bf16 3-term HMMA.
// grid (16, 256), 256 threads (8 warps: 4m x 2n, warp tile 32x32).
// CTA tile 128(M) x 64(N), K = 12 tiles of 64 (3 segs x 256).
// =====================================================================
__global__ void __launch_bounds__(256, 1)
pre_hmma(const __nv_bfloat16* __restrict__ xs_hi, const __nv_bfloat16* __restrict__ xs_lo,
         const __nv_bfloat16* __restrict__ wx_hi, const __nv_bfloat16* __restrict__ wx_lo,
         const float* __restrict__ b1, float* __restrict__ Z) {
    extern __shared__ __align__(128) char pool[];   // 3 x (16KB A + 8KB B) = 73728

    const int tid = threadIdx.x;
    const int w = tid >> 5;
    const int lane = tid & 31;
    const int mw = w & 3, nw = w >> 2;
    const int n0 = blockIdx.x * 64;
    const int m0 = blockIdx.y * 128;

    auto sA = [&](int buf) { return smem_u32(pool) + buf * 16384; };
    auto sB = [&](int buf) { return smem_u32(pool) + 49152 + buf * 8192; };

    auto issue = [&](int kt, int buf) {
        const int seg = kt >> 2;
        const int k0 = (kt & 3) << 6;
        const __nv_bfloat16* Ap = (seg == 1) ? xs_lo : xs_hi;
        const __nv_bfloat16* Bp = (seg == 2) ? wx_lo : wx_hi;
        const uint32_t a = sA(buf), b = sB(buf);
#pragma unroll
        for (int i = 0; i < 4; i++) {           // A: 128 rows x 128B
            const int c = tid + (i << 8);
            const int row = c >> 3, kb = (c & 7) << 4;
            cp_async16(a + row * 128 + (kb ^ ((row & 7) << 4)),
                       (const char*)(Ap + (size_t)(m0 + row) * DIN + k0) + kb);
        }
#pragma unroll
        for (int i = 0; i < 2; i++) {           // B: 64 rows x 128B
            const int c = tid + (i << 8);
            const int row = c >> 3, kb = (c & 7) << 4;
            cp_async16(b + row * 128 + (kb ^ ((row & 7) << 4)),
                       (const char*)(Bp + (size_t)(n0 + row) * DIN + k0) + kb);
        }
    };

    const int l7 = lane & 7;
    const uint32_t xmk = (uint32_t)(l7 << 4);
    const int rowA = ((lane >> 3) & 1) * 8 + l7;
    const uint32_t kselA = ((lane >> 4) & 1) * 16;
    const int rowBb = ((lane >> 4) & 1) * 8 + l7;
    const uint32_t kselB = ((lane >> 3) & 1) * 16;

    float acc[2][4][4];
#pragma unroll
    for (int mt = 0; mt < 2; mt++)
#pragma unroll
        for (int n8 = 0; n8 < 4; n8++)
#pragma unroll
            for (int q = 0; q < 4; q++) acc[mt][n8][q] = 0.0f;

    auto compute = [&](int buf) {
        const uint32_t a = sA(buf), b = sB(buf);
#pragma unroll
        for (int k16 = 0; k16 < 4; k16++) {
            const uint32_t kb = (uint32_t)(k16 * 32);
            uint32_t af[2][4];
#pragma unroll
            for (int mt = 0; mt < 2; mt++)
                ldmatrix_x4(af[mt][0], af[mt][1], af[mt][2], af[mt][3],
                            a + (mw * 32 + mt * 16 + rowA) * 128 + ((kb + kselA) ^ xmk));
#pragma unroll
            for (int nt = 0; nt < 2; nt++) {
                uint32_t b0, b1, b2, b3;
                ldmatrix_x4(b0, b1, b2, b3,
                            b + (nw * 32 + nt * 16 + rowBb) * 128 + ((kb + kselB) ^ xmk));
#pragma unroll
                for (int mt = 0; mt < 2; mt++) {
                    mma_bf16(acc[mt][nt * 2],     af[mt][0], af[mt][1], af[mt][2], af[mt][3], b0, b1);
                    mma_bf16(acc[mt][nt * 2 + 1], af[mt][0], af[mt][1], af[mt][2], af[mt][3], b2, b3);
                }
            }
        }
    };

    issue(0, 0); cp_commit();
    issue(1, 1); cp_commit();
    for (int kt = 0; kt < 12; kt++) {
        cp_wait1();
        __syncthreads();
        if (kt + 2 < 12) issue(kt + 2, (kt + 2) % 3);
        cp_commit();
        compute(kt % 3);
    }

    // epilogue: + b1, write fp32 Z (fragment-wise)
    const int g = lane >> 2, t4 = lane & 3;
#pragma unroll
    for (int mt = 0; mt < 2; mt++)
#pragma unroll
        for (int n8 = 0; n8 < 4; n8++) {
            const float* c = acc[mt][n8];
            const int col = n0 + nw * 32 + n8 * 8 + 2 * t4;
            const int r0 = m0 + mw * 32 + mt * 16 + g;
            const size_t o0 = (size_t)r0 * DH + col;
            const size_t o1 = o0 + 8 * DH;
            float2 bi = *reinterpret_cast<const float2*>(b1 + col);
            *reinterpret_cast<float2*>(Z + o0) = make_float2(c[0] + bi.x, c[1] + bi.y);
            *reinterpret_cast<float2*>(Z + o1) = make_float2(c[2] + bi.x, c[3] + bi.y);
        }
}

// ---------------- packed f32x2 GEMM (readout only) ----------------
__device__ __forceinline__ void fma2(unsigned long long& acc,
                                     unsigned long long a, unsigned long long b) {
    asm("fma.rn.f32x2 %0, %1, %2, %0;" : "+l"(acc) : "l"(a), "l"(b));
}
__device__ __forceinline__ unsigned long long pack2(float x, float y) {
    unsigned long long r;
    asm("mov.b64 %0, {%1, %2};" : "=l"(r) : "f"(x), "f"(y));
    return r;
}
__device__ __forceinline__ float2 unpack2(unsigned long long v) {
    float2 f;
    asm("mov.b64 {%0, %1}, %2;" : "=f"(f.x), "=f"(f.y) : "l"(v));
    return f;
}

template <int BM, int BN, int BK, int TM>
__global__ void __launch_bounds__(256)
gemm_f32x2(const float* __restrict__ A, const float* __restrict__ Bm,
           const float* __restrict__ aux, float* __restrict__ C,
           int M, int N, int K) {
    constexpr int TN = 4;
    constexpr int NT = (BM / TM) * (BN / TN);
    static_assert(NT == 256, "block must be 256 threads");
    __shared__ float As[BK][BM + 4];
    __shared__ float Bs[BK][BN];

    const int tid = threadIdx.x;
    const int n0 = blockIdx.x * BN;
    const int m0 = blockIdx.y * BM;
    constexpr int A_PER = (BM * BK / 4) / NT;
    constexpr int B_PER = (BK * BN / 4) / NT;
    float4 ar[A_PER], br[B_PER];

    auto loadA = [&](int kt) {
#pragma unroll
        for (int i = 0; i < A_PER; i++) {
            int idx = tid + i * NT, row = idx / (BK / 4), kc = idx % (BK / 4);
            ar[i] = *reinterpret_cast<const float4*>(&A[(size_t)(m0 + row) * K + kt * BK + kc * 4]);
        }
    };
    auto storeA = [&]() {
#pragma unroll
        for (int i = 0; i < A_PER; i++) {
            int idx = tid + i * NT, row = idx / (BK / 4), kc = idx % (BK / 4);
            As[kc * 4 + 0][row] = ar[i].x; As[kc * 4 + 1][row] = ar[i].y;
            As[kc * 4 + 2][row] = ar[i].z; As[kc * 4 + 3][row] = ar[i].w;
        }
    };
    auto loadB = [&](int kt) {
#pragma unroll
        for (int i = 0; i < B_PER; i++) {
            int idx = tid + i * NT, kr = idx / (BN / 4), nc = idx % (BN / 4);
            br[i] = *reinterpret_cast<const float4*>(&Bm[(size_t)(kt * BK + kr) * N + n0 + nc * 4]);
        }
    };
    auto storeB = [&]() {
#pragma unroll
        for (int i = 0; i < B_PER; i++) {
            int idx = tid + i * NT, kr = idx / (BN / 4), nc = idx % (BN / 4);
            *reinterpret_cast<float4*>(&Bs[kr][nc * 4]) = br[i];
        }
    };

    unsigned long long acc[TM][2];
#pragma unroll
    for (int i = 0; i < TM; i++) { acc[i][0] = pack2(0, 0); acc[i][1] = pack2(0, 0); }

    const int rg = tid / (BN / TN), cg = tid % (BN / TN);
    const int r0 = rg * TM, c0 = cg * TN;
    const int nk = K / BK;
    loadA(0); loadB(0); storeA(); storeB();
    __syncthreads();
    for (int kt = 0; kt < nk; kt++) {
        if (kt + 1 < nk) { loadA(kt + 1); loadB(kt + 1); }
#pragma unroll
        for (int k = 0; k < BK; k++) {
            float a[TM];
            if (TM == 2) {
                float2 avv = *reinterpret_cast<const float2*>(&As[k][r0]);
                a[0] = avv.x; a[1] = avv.y;
            } else {
                float4 avv = *reinterpret_cast<const float4*>(&As[k][r0]);
                a[0] = avv.x; a[1] = avv.y; a[2] = avv.z; a[3] = avv.w;
            }
            float4 bvv = *reinterpret_cast<const float4*>(&Bs[k][c0]);
            unsigned long long b01 = pack2(bvv.x, bvv.y), b23 = pack2(bvv.z, bvv.w);
#pragma unroll
            for (int i = 0; i < TM; i++) {
                unsigned long long aa = pack2(a[i], a[i]);
                fma2(acc[i][0], aa, b01);
                fma2(acc[i][1], aa, b23);
            }
        }
        __syncthreads();
        if (kt + 1 < nk) { storeA(); storeB(); __syncthreads(); }
    }
#pragma unroll
    for (int i = 0; i < TM; i++) {
        float2 p0 = unpack2(acc[i][0]), p1 = unpack2(acc[i][1]);
        float4 v = make_float4(p0.x, p0.y, p1.x, p1.y);
        const int row = m0 + r0 + i, col = n0 + c0;
        const size_t off = (size_t)row * N + col;
        float s = aux[0];
        v.x += s; v.y += s; v.z += s; v.w += s;
        *reinterpret_cast<float4*>(&C[off]) = v;
    }
}

// ---------------- host launcher ----------------
extern "C" void kernel_launch(void* const* d_in, const int* in_sizes, int n_in,
                              void* d_out, int out_size) {
    const float* xs  = (const float*)d_in[0];
    const float* W1x = (const float*)d_in[1];
    const float* W1h = (const float*)d_in[2];
    const float* b1  = (const float*)d_in[3];
    const float* W2  = (const float*)d_in[4];
    const float* b2  = (const float*)d_in[5];
    float* out = (float*)d_out;

    float *zp, *hf;
    __nv_bfloat16 *hhi, *hlo, *wthi, *wtlo, *xshi, *xslo, *wxhi, *wxlo;
    cudaGetSymbolAddress((void**)&zp, g_z);
    cudaGetSymbolAddress((void**)&hf, g_hf);
    cudaGetSymbolAddress((void**)&hhi, g_h_hi);
    cudaGetSymbolAddress((void**)&hlo, g_h_lo);
    cudaGetSymbolAddress((void**)&wthi, g_wt_hi);
    cudaGetSymbolAddress((void**)&wtlo, g_wt_lo);
    cudaGetSymbolAddress((void**)&xshi, g_xs_hi);
    cudaGetSymbolAddress((void**)&xslo, g_xs_lo);
    cudaGetSymbolAddress((void**)&wxhi, g_w1xt_hi);
    cudaGetSymbolAddress((void**)&wxlo, g_w1xt_lo);

    cudaFuncSetAttribute(pre_hmma, cudaFuncAttributeMaxDynamicSharedMemorySize, 73728);

    const size_t HS = (size_t)BATCH * DH;
    const int XN = T_STEPS * BATCH * DIN;     // 8388608

    // splits
    fsplit_kernel<<<XN / 4 / 256, 256>>>(xs, xshi, xslo, XN / 4);
    wsplit_kernel<<<dim3(DH / 32, DIN / 32), dim3(32, 8)>>>(W1x, wxhi, wxlo, DIN, DH);
    wsplit_kernel<<<dim3(DH / 32, DH / 32), dim3(32, 8)>>>(W1h, wthi, wtlo, DH, DH);

    // zero h ping-pong buffer 0 (hi + lo)
    zero_u4<<<(int)(HS / 8 / 256), 256>>>((uint4*)hhi, (int)(HS / 8));
    zero_u4<<<(int)(HS / 8 / 256), 256>>>((uint4*)hlo, (int)(HS / 8));

    // Z = xs@W1x + b1 (HMMA, 3-term)
    pre_hmma<<<dim3(16, 256), 256, 73728>>>(xshi, xslo, wxhi, wxlo, b1, zp);

    // recurrence
    for (int t = 0; t < T_STEPS; t++) {
        const int cur = t & 1, nxt = cur ^ 1;
        step_hmma<<<dim3(16, 8), 128>>>(
            hhi + cur * HS, hlo + cur * HS, wthi, wtlo,
            zp + (size_t)t * HS,
            hhi + nxt * HS, hlo + nxt * HS,
            (t == T_STEPS - 1) ? hf : nullptr);
    }

    // out = h_final @ W2 + b2
    gemm_f32x2<32, 64, 32, 2>
        <<<dim3(DOUT / 64, BATCH / 32), 256>>>(hf, W2, b2, out, BATCH, DOUT, DH);
}

// round 6
// speedup vs baseline: 4.1362x; 1.0091x over previous
#include <cuda_runtime.h>
#include <cuda_bf16.h>
#include <math.h>
#include <stdint.h>

#define T_STEPS 128
#define BATCH   256
#define DIN     256
#define DH      1024
#define DOUT    256

// ---------------- device scratch ----------------
__device__ float g_z[(size_t)T_STEPS * BATCH * DH];          // 134 MB: xs@W1x + b1
__device__ float g_hf[(size_t)BATCH * DH];                   // fp32 h (final step only)
__device__ __nv_bfloat16 g_h_hi[2][(size_t)BATCH * DH];      // ping-pong split h
__device__ __nv_bfloat16 g_h_lo[2][(size_t)BATCH * DH];
__device__ __nv_bfloat16 g_wt_hi[(size_t)DH * DH];           // W1h^T split: wt[n][k]
__device__ __nv_bfloat16 g_wt_lo[(size_t)DH * DH];
__device__ __nv_bfloat16 g_xs_hi[(size_t)T_STEPS * BATCH * DIN];  // xs split
__device__ __nv_bfloat16 g_xs_lo[(size_t)T_STEPS * BATCH * DIN];
__device__ __nv_bfloat16 g_w1xt_hi[(size_t)DH * DIN];        // W1x^T split
__device__ __nv_bfloat16 g_w1xt_lo[(size_t)DH * DIN];
__device__ int g_bar[T_STEPS];                               // per-step barrier slots

// ---------------- helpers ----------------
__device__ __forceinline__ uint32_t smem_u32(const void* p) {
    uint32_t a;
    asm("{ .reg .u64 t; cvta.to.shared.u64 t, %1; cvt.u32.u64 %0, t; }" : "=r"(a) : "l"(p));
    return a;
}
__device__ __forceinline__ void cp_async16(uint32_t dst, const void* src) {
    asm volatile("cp.async.cg.shared.global [%0], [%1], 16;" :: "r"(dst), "l"(src) : "memory");
}
__device__ __forceinline__ void cp_commit() {
    asm volatile("cp.async.commit_group;" ::: "memory");
}
__device__ __forceinline__ void cp_wait1() {
    asm volatile("cp.async.wait_group 1;" ::: "memory");
}
__device__ __forceinline__ void cp_wait0() {
    asm volatile("cp.async.wait_group 0;" ::: "memory");
}
__device__ __forceinline__ void ldmatrix_x4(uint32_t& r0, uint32_t& r1,
                                            uint32_t& r2, uint32_t& r3, uint32_t addr) {
    asm volatile("ldmatrix.sync.aligned.m8n8.x4.shared.b16 {%0,%1,%2,%3}, [%4];"
                 : "=r"(r0), "=r"(r1), "=r"(r2), "=r"(r3) : "r"(addr));
}
__device__ __forceinline__ void mma_bf16(float* c, uint32_t a0, uint32_t a1,
                                         uint32_t a2, uint32_t a3,
                                         uint32_t b0, uint32_t b1) {
    asm volatile(
        "mma.sync.aligned.m16n8k16.row.col.f32.bf16.bf16.f32 "
        "{%0,%1,%2,%3},{%4,%5,%6,%7},{%8,%9},{%0,%1,%2,%3};"
        : "+f"(c[0]), "+f"(c[1]), "+f"(c[2]), "+f"(c[3])
        : "r"(a0), "r"(a1), "r"(a2), "r"(a3), "r"(b0), "r"(b1));
}
__device__ __forceinline__ float tanh_fast(float x) {
    float ax = fabsf(x);
    float e;
    asm("ex2.approx.f32 %0, %1;" : "=f"(e) : "f"(ax * -2.885390081777927f)); // e^{-2|x|}
    float r = __fdividef(1.0f - e, 1.0f + e);
    return __uint_as_float(__float_as_uint(r) | (__float_as_uint(x) & 0x80000000u));
}
__device__ __forceinline__ uint32_t prmt_hi(uint32_t x, uint32_t y) {
    uint32_t d;
    asm("prmt.b32 %0, %1, %2, 0x7632;" : "=r"(d) : "r"(x), "r"(y));
    return d;
}
__device__ __forceinline__ uint32_t cvt_bf16x2(float hi, float lo) {
    uint32_t d;
    asm("cvt.rn.bf16x2.f32 %0, %1, %2;" : "=r"(d) : "f"(hi), "f"(lo));
    return d;
}

// ---------------- utility kernels ----------------
__global__ void zero_u4(uint4* __restrict__ p, int n4) {
    int i = blockIdx.x * blockDim.x + threadIdx.x;
    if (i < n4) p[i] = make_uint4(0, 0, 0, 0);
}

__global__ void fsplit_kernel(const float* __restrict__ in,
                              __nv_bfloat16* __restrict__ hi,
                              __nv_bfloat16* __restrict__ lo, int n4) {
    int i = blockIdx.x * blockDim.x + threadIdx.x;
    if (i >= n4) return;
    float4 v = reinterpret_cast<const float4*>(in)[i];
    uint32_t u0 = __float_as_uint(v.x), u1 = __float_as_uint(v.y);
    uint32_t u2 = __float_as_uint(v.z), u3 = __float_as_uint(v.w);
    reinterpret_cast<uint2*>(hi)[i] = make_uint2(prmt_hi(u0, u1), prmt_hi(u2, u3));
    float l0 = v.x - __uint_as_float(u0 & 0xFFFF0000u);
    float l1 = v.y - __uint_as_float(u1 & 0xFFFF0000u);
    float l2 = v.z - __uint_as_float(u2 & 0xFFFF0000u);
    float l3 = v.w - __uint_as_float(u3 & 0xFFFF0000u);
    reinterpret_cast<uint2*>(lo)[i] = make_uint2(cvt_bf16x2(l1, l0), cvt_bf16x2(l3, l2));
}

// transpose + bf16 split: W[k][n] (KxN) -> out[n][k]
__global__ void wsplit_kernel(const float* __restrict__ W,
                              __nv_bfloat16* __restrict__ hi,
                              __nv_bfloat16* __restrict__ lo, int K, int N) {
    __shared__ float t[32][33];
    const int tx = threadIdx.x, ty = threadIdx.y;
    const int kb = blockIdx.y * 32, nb = blockIdx.x * 32;
#pragma unroll
    for (int i = 0; i < 32; i += 8)
        t[ty + i][tx] = W[(size_t)(kb + ty + i) * N + nb + tx];
    __syncthreads();
#pragma unroll
    for (int i = 0; i < 32; i += 8) {
        const int n = nb + ty + i, k = kb + tx;
        float v = t[tx][ty + i];
        __nv_bfloat16 h = __float2bfloat16(v);
        hi[(size_t)n * K + k] = h;
        lo[(size_t)n * K + k] = __float2bfloat16(v - __bfloat162float(h));
    }
}

// =====================================================================
// Persistent recurrence kernel: all 128 steps in one launch.
// grid 128 CTAs x 128 threads; CTA c owns tile n0=(c&15)*64, m0=(c>>4)*32.
// Per step: split-K HMMA (as R5), smem reduction, fused tanh epilogue,
// then a device-wide phase barrier (per-step slot in g_bar).
// =====================================================================
__global__ void __launch_bounds__(128, 1)
rnn_persist(const __nv_bfloat16* __restrict__ hhi0, const __nv_bfloat16* __restrict__ hlo0,
            const __nv_bfloat16* __restrict__ wt_hi, const __nv_bfloat16* __restrict__ wt_lo,
            const float* __restrict__ Z, float* __restrict__ o_f,
            int* __restrict__ bar) {
    __shared__ __align__(128) char pool[36864];  // 3x(4KB A + 8KB B); reused for reduction

    const int tid = threadIdx.x;
    const int w = tid >> 5;
    const int lane = tid & 31;
    const int cta = blockIdx.x;
    const int n0 = (cta & 15) * 64;
    const int m0 = (cta >> 4) * 32;
    const size_t HS = (size_t)BATCH * DH;

    const uint32_t poolb = smem_u32(pool);
    auto sA = [&](int buf) { return poolb + buf * 4096; };
    auto sB = [&](int buf) { return poolb + 12288 + buf * 8192; };

    // consumer addressing (constant across steps)
    const int l7 = lane & 7;
    const uint32_t xmk = (uint32_t)(l7 << 4);
    const int rowA = ((lane >> 3) & 1) * 8 + l7;
    const uint32_t kselA = ((lane >> 4) & 1) * 16;
    const int rowBb = ((lane >> 4) & 1) * 8 + l7;
    const uint32_t kselB = ((lane >> 3) & 1) * 16;
    const uint32_t kbyte = (uint32_t)(w * 32);   // this warp's k16 slice

    // producer addressing (constant across steps)
    const int arow = tid >> 3, akb = (tid & 7) << 4;
    const uint32_t adst = arow * 128 + (akb ^ ((arow & 7) << 4));
    const int arow1 = (tid + 128) >> 3;  // second A chunk
    const uint32_t adst1 = arow1 * 128 + (akb ^ ((arow1 & 7) << 4));

    for (int t = 0; t < T_STEPS; t++) {
        const int cur = t & 1;
        const __nv_bfloat16* h_hi = hhi0 + cur * HS;
        const __nv_bfloat16* h_lo = hlo0 + cur * HS;
        __nv_bfloat16* o_hi = const_cast<__nv_bfloat16*>(hhi0) + (cur ^ 1) * HS;
        __nv_bfloat16* o_lo = const_cast<__nv_bfloat16*>(hlo0) + (cur ^ 1) * HS;
        const float* Zt = Z + (size_t)t * HS;

        auto issue = [&](int kt, int buf) {
            const int seg = kt >> 4;
            const int k0 = (kt & 15) << 6;
            const __nv_bfloat16* Ap = (seg == 1) ? h_lo : h_hi;
            const __nv_bfloat16* Bp = (seg == 2) ? wt_lo : wt_hi;
            const uint32_t a = sA(buf), b = sB(buf);
            cp_async16(a + adst,
                       (const char*)(Ap + (size_t)(m0 + arow) * DH + k0) + akb);
            cp_async16(a + adst1,
                       (const char*)(Ap + (size_t)(m0 + arow1) * DH + k0) + akb);
#pragma unroll
            for (int i = 0; i < 4; i++) {       // B: 64 rows x 128B
                const int c = tid + (i << 7);
                const int row = c >> 3, kb = (c & 7) << 4;
                cp_async16(b + row * 128 + (kb ^ ((row & 7) << 4)),
                           (const char*)(Bp + (size_t)(n0 + row) * DH + k0) + kb);
            }
        };

        float acc[2][8][4];
#pragma unroll
        for (int mt = 0; mt < 2; mt++)
#pragma unroll
            for (int n8 = 0; n8 < 8; n8++)
#pragma unroll
                for (int q = 0; q < 4; q++) acc[mt][n8][q] = 0.0f;

        auto compute = [&](int buf) {
            const uint32_t a = sA(buf), b = sB(buf);
            uint32_t af[2][4];
#pragma unroll
            for (int mt = 0; mt < 2; mt++)
                ldmatrix_x4(af[mt][0], af[mt][1], af[mt][2], af[mt][3],
                            a + (mt * 16 + rowA) * 128 + ((kbyte + kselA) ^ xmk));
#pragma unroll
            for (int nt = 0; nt < 4; nt++) {
                uint32_t b0, b1, b2, b3;
                ldmatrix_x4(b0, b1, b2, b3,
                            b + (nt * 16 + rowBb) * 128 + ((kbyte + kselB) ^ xmk));
#pragma unroll
                for (int mt = 0; mt < 2; mt++) {
                    mma_bf16(acc[mt][nt * 2],     af[mt][0], af[mt][1], af[mt][2], af[mt][3], b0, b1);
                    mma_bf16(acc[mt][nt * 2 + 1], af[mt][0], af[mt][1], af[mt][2], af[mt][3], b2, b3);
                }
            }
        };

        issue(0, 0); cp_commit();
        issue(1, 1); cp_commit();
        for (int kt = 0; kt < 48; kt++) {
            cp_wait1();
            __syncthreads();
            if (kt + 2 < 48) issue(kt + 2, (kt + 2) % 3);
            cp_commit();
            compute(kt % 3);
        }

        // ---- cross-warp reduction through smem ----
        cp_wait0();
        __syncthreads();
        constexpr int RP = 68;
        float* sred = reinterpret_cast<float*>(pool);   // [4][32][68]
        float* ms = sred + w * (32 * RP);
        const int g = lane >> 2, t4 = lane & 3;
#pragma unroll
        for (int mt = 0; mt < 2; mt++)
#pragma unroll
            for (int n8 = 0; n8 < 8; n8++) {
                const int r0 = mt * 16 + g, c = n8 * 8 + 2 * t4;
                *reinterpret_cast<float2*>(&ms[r0 * RP + c]) =
                    make_float2(acc[mt][n8][0], acc[mt][n8][1]);
                *reinterpret_cast<float2*>(&ms[(r0 + 8) * RP + c]) =
                    make_float2(acc[mt][n8][2], acc[mt][n8][3]);
            }
        __syncthreads();

        // ---- fused epilogue ----
        const int row = tid >> 2;
        const int c0 = (tid & 3) * 16;
#pragma unroll
        for (int q = 0; q < 4; q++) {
            const int col = c0 + q * 4;
            float4 s = *reinterpret_cast<const float4*>(&sred[row * RP + col]);
#pragma unroll
            for (int w2 = 1; w2 < 4; w2++) {
                float4 p = *reinterpret_cast<const float4*>(&sred[w2 * 32 * RP + row * RP + col]);
                s.x += p.x; s.y += p.y; s.z += p.z; s.w += p.w;
            }
            const size_t off = (size_t)(m0 + row) * DH + n0 + col;
            float4 z = *reinterpret_cast<const float4*>(Zt + off);
            float v0 = tanh_fast(s.x + z.x);
            float v1 = tanh_fast(s.y + z.y);
            float v2 = tanh_fast(s.z + z.z);
            float v3 = tanh_fast(s.w + z.w);
            if (t == T_STEPS - 1)
                *reinterpret_cast<float4*>(o_f + off) = make_float4(v0, v1, v2, v3);
            uint32_t u0 = __float_as_uint(v0), u1 = __float_as_uint(v1);
            uint32_t u2 = __float_as_uint(v2), u3 = __float_as_uint(v3);
            *reinterpret_cast<uint2*>(o_hi + off) = make_uint2(prmt_hi(u0, u1), prmt_hi(u2, u3));
            float l0 = v0 - __uint_as_float(u0 & 0xFFFF0000u);
            float l1 = v1 - __uint_as_float(u1 & 0xFFFF0000u);
            float l2 = v2 - __uint_as_float(u2 & 0xFFFF0000u);
            float l3 = v3 - __uint_as_float(u3 & 0xFFFF0000u);
            *reinterpret_cast<uint2*>(o_lo + off) = make_uint2(cvt_bf16x2(l1, l0), cvt_bf16x2(l3, l2));
        }

        // ---- device-wide phase barrier (skip after last step) ----
        if (t < T_STEPS - 1) {
            __syncthreads();           // all threads in CTA done writing h
            if (tid == 0) {
                int* slot = bar + t;
                asm volatile("red.release.gpu.global.add.s32 [%0], 1;" :: "l"(slot) : "memory");
                int v;
                do {
                    __nanosleep(64);
                    asm volatile("ld.acquire.gpu.global.b32 %0, [%1];" : "=r"(v) : "l"(slot) : "memory");
                } while (v < 128);
            }
            __syncthreads();
        }
    }
}

// =====================================================================
// Precompute kernel: Z = xs @ W1x + b1, fp32 via bf16 3-term HMMA.
// =====================================================================
__global__ void __launch_bounds__(256, 1)
pre_hmma(const __nv_bfloat16* __restrict__ xs_hi, const __nv_bfloat16* __restrict__ xs_lo,
         const __nv_bfloat16* __restrict__ wx_hi, const __nv_bfloat16* __restrict__ wx_lo,
         const float* __restrict__ b1, float* __restrict__ Z) {
    extern __shared__ __align__(128) char pool[];   // 3 x (16KB A + 8KB B)

    const int tid = threadIdx.x;
    const int w = tid >> 5;
    const int lane = tid & 31;
    const int mw = w & 3, nw = w >> 2;
    const int n0 = blockIdx.x * 64;
    const int m0 = blockIdx.y * 128;

    auto sA = [&](int buf) { return smem_u32(pool) + buf * 16384; };
    auto sB = [&](int buf) { return smem_u32(pool) + 49152 + buf * 8192; };

    auto issue = [&](int kt, int buf) {
        const int seg = kt >> 2;
        const int k0 = (kt & 3) << 6;
        const __nv_bfloat16* Ap = (seg == 1) ? xs_lo : xs_hi;
        const __nv_bfloat16* Bp = (seg == 2) ? wx_lo : wx_hi;
        const uint32_t a = sA(buf), b = sB(buf);
#pragma unroll
        for (int i = 0; i < 4; i++) {
            const int c = tid + (i << 8);
            const int row = c >> 3, kb = (c & 7) << 4;
            cp_async16(a + row * 128 + (kb ^ ((row & 7) << 4)),
                       (const char*)(Ap + (size_t)(m0 + row) * DIN + k0) + kb);
        }
#pragma unroll
        for (int i = 0; i < 2; i++) {
            const int c = tid + (i << 8);
            const int row = c >> 3, kb = (c & 7) << 4;
            cp_async16(b + row * 128 + (kb ^ ((row & 7) << 4)),
                       (const char*)(Bp + (size_t)(n0 + row) * DIN + k0) + kb);
        }
    };

    const int l7 = lane & 7;
    const uint32_t xmk = (uint32_t)(l7 << 4);
    const int rowA = ((lane >> 3) & 1) * 8 + l7;
    const uint32_t kselA = ((lane >> 4) & 1) * 16;
    const int rowBb = ((lane >> 4) & 1) * 8 + l7;
    const uint32_t kselB = ((lane >> 3) & 1) * 16;

    float acc[2][4][4];
#pragma unroll
    for (int mt = 0; mt < 2; mt++)
#pragma unroll
        for (int n8 = 0; n8 < 4; n8++)
#pragma unroll
            for (int q = 0; q < 4; q++) acc[mt][n8][q] = 0.0f;

    auto compute = [&](int buf) {
        const uint32_t a = sA(buf), b = sB(buf);
#pragma unroll
        for (int k16 = 0; k16 < 4; k16++) {
            const uint32_t kb = (uint32_t)(k16 * 32);
            uint32_t af[2][4];
#pragma unroll
            for (int mt = 0; mt < 2; mt++)
                ldmatrix_x4(af[mt][0], af[mt][1], af[mt][2], af[mt][3],
                            a + (mw * 32 + mt * 16 + rowA) * 128 + ((kb + kselA) ^ xmk));
#pragma unroll
            for (int nt = 0; nt < 2; nt++) {
                uint32_t b0, b1, b2, b3;
                ldmatrix_x4(b0, b1, b2, b3,
                            b + (nw * 32 + nt * 16 + rowBb) * 128 + ((kb + kselB) ^ xmk));
#pragma unroll
                for (int mt = 0; mt < 2; mt++) {
                    mma_bf16(acc[mt][nt * 2],     af[mt][0], af[mt][1], af[mt][2], af[mt][3], b0, b1);
                    mma_bf16(acc[mt][nt * 2 + 1], af[mt][0], af[mt][1], af[mt][2], af[mt][3], b2, b3);
                }
            }
        }
    };

    issue(0, 0); cp_commit();
    issue(1, 1); cp_commit();
    for (int kt = 0; kt < 12; kt++) {
        cp_wait1();
        __syncthreads();
        if (kt + 2 < 12) issue(kt + 2, (kt + 2) % 3);
        cp_commit();
        compute(kt % 3);
    }

    const int g = lane >> 2, t4 = lane & 3;
#pragma unroll
    for (int mt = 0; mt < 2; mt++)
#pragma unroll
        for (int n8 = 0; n8 < 4; n8++) {
            const float* c = acc[mt][n8];
            const int col = n0 + nw * 32 + n8 * 8 + 2 * t4;
            const int r0 = m0 + mw * 32 + mt * 16 + g;
            const size_t o0 = (size_t)r0 * DH + col;
            const size_t o1 = o0 + 8 * DH;
            float2 bi = *reinterpret_cast<const float2*>(b1 + col);
            *reinterpret_cast<float2*>(Z + o0) = make_float2(c[0] + bi.x, c[1] + bi.y);
            *reinterpret_cast<float2*>(Z + o1) = make_float2(c[2] + bi.x, c[3] + bi.y);
        }
}

// ---------------- packed f32x2 GEMM (readout only) ----------------
__device__ __forceinline__ void fma2(unsigned long long& acc,
                                     unsigned long long a, unsigned long long b) {
    asm("fma.rn.f32x2 %0, %1, %2, %0;" : "+l"(acc) : "l"(a), "l"(b));
}
__device__ __forceinline__ unsigned long long pack2(float x, float y) {
    unsigned long long r;
    asm("mov.b64 %0, {%1, %2};" : "=l"(r) : "f"(x), "f"(y));
    return r;
}
__device__ __forceinline__ float2 unpack2(unsigned long long v) {
    float2 f;
    asm("mov.b64 {%0, %1}, %2;" : "=f"(f.x), "=f"(f.y) : "l"(v));
    return f;
}

template <int BM, int BN, int BK, int TM>
__global__ void __launch_bounds__(256)
gemm_f32x2(const float* __restrict__ A, const float* __restrict__ Bm,
           const float* __restrict__ aux, float* __restrict__ C,
           int M, int N, int K) {
    constexpr int TN = 4;
    constexpr int NT = (BM / TM) * (BN / TN);
    static_assert(NT == 256, "block must be 256 threads");
    __shared__ float As[BK][BM + 4];
    __shared__ float Bs[BK][BN];

    const int tid = threadIdx.x;
    const int n0 = blockIdx.x * BN;
    const int m0 = blockIdx.y * BM;
    constexpr int A_PER = (BM * BK / 4) / NT;
    constexpr int B_PER = (BK * BN / 4) / NT;
    float4 ar[A_PER], br[B_PER];

    auto loadA = [&](int kt) {
#pragma unroll
        for (int i = 0; i < A_PER; i++) {
            int idx = tid + i * NT, row = idx / (BK / 4), kc = idx % (BK / 4);
            ar[i] = *reinterpret_cast<const float4*>(&A[(size_t)(m0 + row) * K + kt * BK + kc * 4]);
        }
    };
    auto storeA = [&]() {
#pragma unroll
        for (int i = 0; i < A_PER; i++) {
            int idx = tid + i * NT, row = idx / (BK / 4), kc = idx % (BK / 4);
            As[kc * 4 + 0][row] = ar[i].x; As[kc * 4 + 1][row] = ar[i].y;
            As[kc * 4 + 2][row] = ar[i].z; As[kc * 4 + 3][row] = ar[i].w;
        }
    };
    auto loadB = [&](int kt) {
#pragma unroll
        for (int i = 0; i < B_PER; i++) {
            int idx = tid + i * NT, kr = idx / (BN / 4), nc = idx % (BN / 4);
            br[i] = *reinterpret_cast<const float4*>(&Bm[(size_t)(kt * BK + kr) * N + n0 + nc * 4]);
        }
    };
    auto storeB = [&]() {
#pragma unroll
        for (int i = 0; i < B_PER; i++) {
            int idx = tid + i * NT, kr = idx / (BN / 4), nc = idx % (BN / 4);
            *reinterpret_cast<float4*>(&Bs[kr][nc * 4]) = br[i];
        }
    };

    unsigned long long acc[TM][2];
#pragma unroll
    for (int i = 0; i < TM; i++) { acc[i][0] = pack2(0, 0); acc[i][1] = pack2(0, 0); }

    const int rg = tid / (BN / TN), cg = tid % (BN / TN);
    const int r0 = rg * TM, c0 = cg * TN;
    const int nk = K / BK;
    loadA(0); loadB(0); storeA(); storeB();
    __syncthreads();
    for (int kt = 0; kt < nk; kt++) {
        if (kt + 1 < nk) { loadA(kt + 1); loadB(kt + 1); }
#pragma unroll
        for (int k = 0; k < BK; k++) {
            float a[TM];
            if (TM == 2) {
                float2 avv = *reinterpret_cast<const float2*>(&As[k][r0]);
                a[0] = avv.x; a[1] = avv.y;
            } else {
                float4 avv = *reinterpret_cast<const float4*>(&As[k][r0]);
                a[0] = avv.x; a[1] = avv.y; a[2] = avv.z; a[3] = avv.w;
            }
            float4 bvv = *reinterpret_cast<const float4*>(&Bs[k][c0]);
            unsigned long long b01 = pack2(bvv.x, bvv.y), b23 = pack2(bvv.z, bvv.w);
#pragma unroll
            for (int i = 0; i < TM; i++) {
                unsigned long long aa = pack2(a[i], a[i]);
                fma2(acc[i][0], aa, b01);
                fma2(acc[i][1], aa, b23);
            }
        }
        __syncthreads();
        if (kt + 1 < nk) { storeA(); storeB(); __syncthreads(); }
    }
#pragma unroll
    for (int i = 0; i < TM; i++) {
        float2 p0 = unpack2(acc[i][0]), p1 = unpack2(acc[i][1]);
        float4 v = make_float4(p0.x, p0.y, p1.x, p1.y);
        const int row = m0 + r0 + i, col = n0 + c0;
        const size_t off = (size_t)row * N + col;
        float s = aux[0];
        v.x += s; v.y += s; v.z += s; v.w += s;
        *reinterpret_cast<float4*>(&C[off]) = v;
    }
}

// ---------------- host launcher ----------------
extern "C" void kernel_launch(void* const* d_in, const int* in_sizes, int n_in,
                              void* d_out, int out_size) {
    const float* xs  = (const float*)d_in[0];
    const float* W1x = (const float*)d_in[1];
    const float* W1h = (const float*)d_in[2];
    const float* b1  = (const float*)d_in[3];
    const float* W2  = (const float*)d_in[4];
    const float* b2  = (const float*)d_in[5];
    float* out = (float*)d_out;

    float *zp, *hf;
    int* barp;
    __nv_bfloat16 *hhi, *hlo, *wthi, *wtlo, *xshi, *xslo, *wxhi, *wxlo;
    cudaGetSymbolAddress((void**)&zp, g_z);
    cudaGetSymbolAddress((void**)&hf, g_hf);
    cudaGetSymbolAddress((void**)&hhi, g_h_hi);
    cudaGetSymbolAddress((void**)&hlo, g_h_lo);
    cudaGetSymbolAddress((void**)&wthi, g_wt_hi);
    cudaGetSymbolAddress((void**)&wtlo, g_wt_lo);
    cudaGetSymbolAddress((void**)&xshi, g_xs_hi);
    cudaGetSymbolAddress((void**)&xslo, g_xs_lo);
    cudaGetSymbolAddress((void**)&wxhi, g_w1xt_hi);
    cudaGetSymbolAddress((void**)&wxlo, g_w1xt_lo);
    cudaGetSymbolAddress((void**)&barp, g_bar);

    cudaFuncSetAttribute(pre_hmma, cudaFuncAttributeMaxDynamicSharedMemorySize, 73728);

    const size_t HS = (size_t)BATCH * DH;
    const int XN = T_STEPS * BATCH * DIN;

    // splits
    fsplit_kernel<<<XN / 4 / 256, 256>>>(xs, xshi, xslo, XN / 4);
    wsplit_kernel<<<dim3(DH / 32, DIN / 32), dim3(32, 8)>>>(W1x, wxhi, wxlo, DIN, DH);
    wsplit_kernel<<<dim3(DH / 32, DH / 32), dim3(32, 8)>>>(W1h, wthi, wtlo, DH, DH);

    // zero h ping-pong buffer 0 (hi + lo) and barrier slots
    zero_u4<<<(int)(HS / 8 / 256), 256>>>((uint4*)hhi, (int)(HS / 8));
    zero_u4<<<(int)(HS / 8 / 256), 256>>>((uint4*)hlo, (int)(HS / 8));
    zero_u4<<<1, 32>>>((uint4*)barp, T_STEPS / 4);

    // Z = xs@W1x + b1 (HMMA, 3-term)
    pre_hmma<<<dim3(16, 256), 256, 73728>>>(xshi, xslo, wxhi, wxlo, b1, zp);

    // full recurrence in one persistent launch
    rnn_persist<<<128, 128>>>(hhi, hlo, wthi, wtlo, zp, hf, barp);

    // out = h_final @ W2 + b2
    gemm_f32x2<32, 64, 32, 2>
        <<<dim3(DOUT / 64, BATCH / 32), 256>>>(hf, W2, b2, out, BATCH, DOUT, DH);
}

// round 7
// speedup vs baseline: 7.3792x; 1.7841x over previous
#include <cuda_runtime.h>
#include <cuda_bf16.h>
#include <math.h>
#include <stdint.h>

#define T_STEPS 128
#define BATCH   256
#define DIN     256
#define DH      1024
#define DOUT    256

// ---------------- device scratch ----------------
__device__ float g_z[(size_t)T_STEPS * BATCH * DH];          // 134 MB: xs@W1x + b1
__device__ float g_hf[(size_t)BATCH * DH];                   // fp32 h (final step only)
__device__ __nv_bfloat16 g_h_hi[2][(size_t)BATCH * DH];      // ping-pong split h
__device__ __nv_bfloat16 g_h_lo[2][(size_t)BATCH * DH];
__device__ __nv_bfloat16 g_wt_hi[(size_t)DH * DH];           // W1h^T split: wt[n][k]
__device__ __nv_bfloat16 g_wt_lo[(size_t)DH * DH];
__device__ __nv_bfloat16 g_xs_hi[(size_t)T_STEPS * BATCH * DIN];  // xs split
__device__ __nv_bfloat16 g_xs_lo[(size_t)T_STEPS * BATCH * DIN];
__device__ __nv_bfloat16 g_w1xt_hi[(size_t)DH * DIN];        // W1x^T split
__device__ __nv_bfloat16 g_w1xt_lo[(size_t)DH * DIN];
__device__ int g_bar[T_STEPS];                               // per-step barrier slots

// ---------------- helpers ----------------
__device__ __forceinline__ uint32_t smem_u32(const void* p) {
    uint32_t a;
    asm("{ .reg .u64 t; cvta.to.shared.u64 t, %1; cvt.u32.u64 %0, t; }" : "=r"(a) : "l"(p));
    return a;
}
__device__ __forceinline__ void cp_async16(uint32_t dst, const void* src) {
    asm volatile("cp.async.cg.shared.global [%0], [%1], 16;" :: "r"(dst), "l"(src) : "memory");
}
__device__ __forceinline__ void cp_commit() {
    asm volatile("cp.async.commit_group;" ::: "memory");
}
__device__ __forceinline__ void cp_wait1() {
    asm volatile("cp.async.wait_group 1;" ::: "memory");
}
__device__ __forceinline__ void cp_wait0() {
    asm volatile("cp.async.wait_group 0;" ::: "memory");
}
__device__ __forceinline__ void ldmatrix_x4(uint32_t* r, uint32_t addr) {
    asm volatile("ldmatrix.sync.aligned.m8n8.x4.shared.b16 {%0,%1,%2,%3}, [%4];"
                 : "=r"(r[0]), "=r"(r[1]), "=r"(r[2]), "=r"(r[3]) : "r"(addr));
}
__device__ __forceinline__ void mma_bf16(float* c, const uint32_t* a,
                                         uint32_t b0, uint32_t b1) {
    asm volatile(
        "mma.sync.aligned.m16n8k16.row.col.f32.bf16.bf16.f32 "
        "{%0,%1,%2,%3},{%4,%5,%6,%7},{%8,%9},{%0,%1,%2,%3};"
        : "+f"(c[0]), "+f"(c[1]), "+f"(c[2]), "+f"(c[3])
        : "r"(a[0]), "r"(a[1]), "r"(a[2]), "r"(a[3]), "r"(b0), "r"(b1));
}
__device__ __forceinline__ float tanh_fast(float x) {
    float ax = fabsf(x);
    float e;
    asm("ex2.approx.f32 %0, %1;" : "=f"(e) : "f"(ax * -2.885390081777927f)); // e^{-2|x|}
    float r = __fdividef(1.0f - e, 1.0f + e);
    return __uint_as_float(__float_as_uint(r) | (__float_as_uint(x) & 0x80000000u));
}
__device__ __forceinline__ uint32_t prmt_hi(uint32_t x, uint32_t y) {
    uint32_t d;
    asm("prmt.b32 %0, %1, %2, 0x7632;" : "=r"(d) : "r"(x), "r"(y));
    return d;
}
__device__ __forceinline__ uint32_t cvt_bf16x2(float hi, float lo) {
    uint32_t d;
    asm("cvt.rn.bf16x2.f32 %0, %1, %2;" : "=r"(d) : "f"(hi), "f"(lo));
    return d;
}

// ---------------- utility kernels ----------------
__global__ void zero_u4(uint4* __restrict__ p, int n4) {
    int i = blockIdx.x * blockDim.x + threadIdx.x;
    if (i < n4) p[i] = make_uint4(0, 0, 0, 0);
}

__global__ void fsplit_kernel(const float* __restrict__ in,
                              __nv_bfloat16* __restrict__ hi,
                              __nv_bfloat16* __restrict__ lo, int n4) {
    int i = blockIdx.x * blockDim.x + threadIdx.x;
    if (i >= n4) return;
    float4 v = reinterpret_cast<const float4*>(in)[i];
    uint32_t u0 = __float_as_uint(v.x), u1 = __float_as_uint(v.y);
    uint32_t u2 = __float_as_uint(v.z), u3 = __float_as_uint(v.w);
    reinterpret_cast<uint2*>(hi)[i] = make_uint2(prmt_hi(u0, u1), prmt_hi(u2, u3));
    float l0 = v.x - __uint_as_float(u0 & 0xFFFF0000u);
    float l1 = v.y - __uint_as_float(u1 & 0xFFFF0000u);
    float l2 = v.z - __uint_as_float(u2 & 0xFFFF0000u);
    float l3 = v.w - __uint_as_float(u3 & 0xFFFF0000u);
    reinterpret_cast<uint2*>(lo)[i] = make_uint2(cvt_bf16x2(l1, l0), cvt_bf16x2(l3, l2));
}

// transpose + bf16 split: W[k][n] (KxN) -> out[n][k]
__global__ void wsplit_kernel(const float* __restrict__ W,
                              __nv_bfloat16* __restrict__ hi,
                              __nv_bfloat16* __restrict__ lo, int K, int N) {
    __shared__ float t[32][33];
    const int tx = threadIdx.x, ty = threadIdx.y;
    const int kb = blockIdx.y * 32, nb = blockIdx.x * 32;
#pragma unroll
    for (int i = 0; i < 32; i += 8)
        t[ty + i][tx] = W[(size_t)(kb + ty + i) * N + nb + tx];
    __syncthreads();
#pragma unroll
    for (int i = 0; i < 32; i += 8) {
        const int n = nb + ty + i, k = kb + tx;
        float v = t[tx][ty + i];
        __nv_bfloat16 h = __float2bfloat16(v);
        hi[(size_t)n * K + k] = h;
        lo[(size_t)n * K + k] = __float2bfloat16(v - __bfloat162float(h));
    }
}

// =====================================================================
// Persistent recurrence kernel, W1h slice RESIDENT in shared memory.
// grid 128 CTAs x 256 threads; CTA c: n0=(c&31)*32, m0=(c>>5)*64.
// smem: W_hi[32][1024]bf16 (64KB) + W_lo (64KB) + 3 stages of
//       (A_hi[64][128] + A_lo[64][128]) bf16 (32KB each) = 224KB.
// Per step: 8 k-tiles of 128; 8 warps split-K (warp w owns k16 slice w);
// 3-term accumulate (ahi*bhi + alo*bhi + ahi*blo); smem reduction;
// fused tanh epilogue; device-wide per-step barrier.
// =====================================================================
#define W_HI_OFF  0
#define W_LO_OFF  65536
#define ST_OFF    131072
#define ST_SZ     32768
#define SMEM_TOT  229376
#define RP 36
#define WBP 2308

__global__ void __launch_bounds__(256, 1)
rnn_persist(const __nv_bfloat16* __restrict__ hhi0, const __nv_bfloat16* __restrict__ hlo0,
            const __nv_bfloat16* __restrict__ wt_hi, const __nv_bfloat16* __restrict__ wt_lo,
            const float* __restrict__ Z, float* __restrict__ o_f,
            int* __restrict__ bar) {
    extern __shared__ __align__(128) char sm[];
    const uint32_t sb = smem_u32(sm);

    const int tid = threadIdx.x;
    const int w = tid >> 5;
    const int lane = tid & 31;
    const int cta = blockIdx.x;
    const int n0 = (cta & 31) * 32;
    const int m0 = (cta >> 5) * 64;
    const size_t HS = (size_t)BATCH * DH;

    // ---- load W slice into smem once (hi: rows n0..n0+31, pitch 2048B) ----
    {
#pragma unroll
        for (int i = 0; i < 16; i++) {
            const int c = tid + i * 256;            // 4096 chunks of 16B
            const int row = c >> 7, u = c & 127;    // 128 units per 2048B row
            cp_async16(sb + W_HI_OFF + row * 2048 + ((u * 16) ^ ((row & 7) << 4)),
                       wt_hi + (size_t)(n0 + row) * DH + u * 8);
        }
#pragma unroll
        for (int i = 0; i < 16; i++) {
            const int c = tid + i * 256;
            const int row = c >> 7, u = c & 127;
            cp_async16(sb + W_LO_OFF + row * 2048 + ((u * 16) ^ ((row & 7) << 4)),
                       wt_lo + (size_t)(n0 + row) * DH + u * 8);
        }
        cp_commit();
    }

    // consumer addressing (constant across steps)
    const int l7 = lane & 7;
    const uint32_t xmk = (uint32_t)(l7 << 4);
    const int rowA = ((lane >> 3) & 1) * 8 + l7;
    const uint32_t kselA = ((lane >> 4) & 1) * 16;
    const int rowBb = ((lane >> 4) & 1) * 8 + l7;
    const uint32_t kselB = ((lane >> 3) & 1) * 16;
    const uint32_t wkb = (uint32_t)(w * 32);       // warp's k16 slice (bytes)

    for (int t = 0; t < T_STEPS; t++) {
        const int cur = t & 1;
        const __nv_bfloat16* h_hi = hhi0 + cur * HS;
        const __nv_bfloat16* h_lo = hlo0 + cur * HS;
        __nv_bfloat16* o_hi = const_cast<__nv_bfloat16*>(hhi0) + (cur ^ 1) * HS;
        __nv_bfloat16* o_lo = const_cast<__nv_bfloat16*>(hlo0) + (cur ^ 1) * HS;
        const float* Zt = Z + (size_t)t * HS;

        // issue one 128-k A tile (hi + lo) into stage buf
        auto issue = [&](int kt, int buf) {
            const int k0 = kt << 7;
            const uint32_t st = sb + ST_OFF + buf * ST_SZ;
#pragma unroll
            for (int i = 0; i < 4; i++) {           // A_hi: 64 rows x 256B
                const int c = tid + (i << 8);
                const int row = c >> 4, u = c & 15;
                cp_async16(st + row * 256 + ((u * 16) ^ ((row & 7) << 4)),
                           h_hi + (size_t)(m0 + row) * DH + k0 + u * 8);
            }
#pragma unroll
            for (int i = 0; i < 4; i++) {           // A_lo
                const int c = tid + (i << 8);
                const int row = c >> 4, u = c & 15;
                cp_async16(st + 16384 + row * 256 + ((u * 16) ^ ((row & 7) << 4)),
                           h_lo + (size_t)(m0 + row) * DH + k0 + u * 8);
            }
        };

        float acc[4][4][4];
#pragma unroll
        for (int mt = 0; mt < 4; mt++)
#pragma unroll
            for (int n8 = 0; n8 < 4; n8++)
#pragma unroll
                for (int q = 0; q < 4; q++) acc[mt][n8][q] = 0.0f;

        auto compute = [&](int kt, int buf) {
            const uint32_t aHi = sb + ST_OFF + buf * ST_SZ;
            const uint32_t aLo = aHi + 16384;
            const uint32_t tkb = (uint32_t)(kt << 8);  // tile byte offset in W rows
            uint32_t ah[4][4], al[4][4], bh[2][4], bl[2][4];
#pragma unroll
            for (int mt = 0; mt < 4; mt++) {
                ldmatrix_x4(ah[mt], aHi + (mt * 16 + rowA) * 256 + ((wkb + kselA) ^ xmk));
                ldmatrix_x4(al[mt], aLo + (mt * 16 + rowA) * 256 + ((wkb + kselA) ^ xmk));
            }
#pragma unroll
            for (int nt = 0; nt < 2; nt++) {
                ldmatrix_x4(bh[nt], sb + W_HI_OFF + (nt * 16 + rowBb) * 2048 +
                                        ((tkb + wkb + kselB) ^ xmk));
                ldmatrix_x4(bl[nt], sb + W_LO_OFF + (nt * 16 + rowBb) * 2048 +
                                        ((tkb + wkb + kselB) ^ xmk));
            }
#pragma unroll
            for (int mt = 0; mt < 4; mt++)
#pragma unroll
                for (int nt = 0; nt < 2; nt++) {
                    mma_bf16(acc[mt][nt * 2],     ah[mt], bh[nt][0], bh[nt][1]);
                    mma_bf16(acc[mt][nt * 2 + 1], ah[mt], bh[nt][2], bh[nt][3]);
                    mma_bf16(acc[mt][nt * 2],     al[mt], bh[nt][0], bh[nt][1]);
                    mma_bf16(acc[mt][nt * 2 + 1], al[mt], bh[nt][2], bh[nt][3]);
                    mma_bf16(acc[mt][nt * 2],     ah[mt], bl[nt][0], bl[nt][1]);
                    mma_bf16(acc[mt][nt * 2 + 1], ah[mt], bl[nt][2], bl[nt][3]);
                }
        };

        issue(0, 0); cp_commit();
        issue(1, 1); cp_commit();
        for (int kt = 0; kt < 8; kt++) {
            cp_wait1();
            __syncthreads();
            if (kt + 2 < 8) issue(kt + 2, (kt + 2) % 3);
            cp_commit();
            compute(kt, kt % 3);
        }

        // ---- cross-warp split-K reduction through smem (reuse stages) ----
        cp_wait0();
        __syncthreads();
        float* sred = reinterpret_cast<float*>(sm + ST_OFF);
        float* ms = sred + w * WBP;
        const int g = lane >> 2, t4 = lane & 3;
#pragma unroll
        for (int mt = 0; mt < 4; mt++)
#pragma unroll
            for (int n8 = 0; n8 < 4; n8++) {
                const int r0 = mt * 16 + g, c = n8 * 8 + 2 * t4;
                *reinterpret_cast<float2*>(&ms[r0 * RP + c]) =
                    make_float2(acc[mt][n8][0], acc[mt][n8][1]);
                *reinterpret_cast<float2*>(&ms[(r0 + 8) * RP + c]) =
                    make_float2(acc[mt][n8][2], acc[mt][n8][3]);
            }
        __syncthreads();

        // ---- fused epilogue: sum 8 partials + Z, tanh, store splits ----
        const int row = tid >> 2;
        const int c0 = (tid & 3) * 8;
#pragma unroll
        for (int q = 0; q < 2; q++) {
            const int col = c0 + q * 4;
            float4 s = *reinterpret_cast<const float4*>(&sred[row * RP + col]);
#pragma unroll
            for (int w2 = 1; w2 < 8; w2++) {
                float4 p = *reinterpret_cast<const float4*>(&sred[w2 * WBP + row * RP + col]);
                s.x += p.x; s.y += p.y; s.z += p.z; s.w += p.w;
            }
            const size_t off = (size_t)(m0 + row) * DH + n0 + col;
            float4 z = *reinterpret_cast<const float4*>(Zt + off);
            float v0 = tanh_fast(s.x + z.x);
            float v1 = tanh_fast(s.y + z.y);
            float v2 = tanh_fast(s.z + z.z);
            float v3 = tanh_fast(s.w + z.w);
            if (t == T_STEPS - 1)
                *reinterpret_cast<float4*>(o_f + off) = make_float4(v0, v1, v2, v3);
            uint32_t u0 = __float_as_uint(v0), u1 = __float_as_uint(v1);
            uint32_t u2 = __float_as_uint(v2), u3 = __float_as_uint(v3);
            *reinterpret_cast<uint2*>(o_hi + off) = make_uint2(prmt_hi(u0, u1), prmt_hi(u2, u3));
            float l0 = v0 - __uint_as_float(u0 & 0xFFFF0000u);
            float l1 = v1 - __uint_as_float(u1 & 0xFFFF0000u);
            float l2 = v2 - __uint_as_float(u2 & 0xFFFF0000u);
            float l3 = v3 - __uint_as_float(u3 & 0xFFFF0000u);
            *reinterpret_cast<uint2*>(o_lo + off) = make_uint2(cvt_bf16x2(l1, l0), cvt_bf16x2(l3, l2));
        }

        // ---- device-wide phase barrier (skip after last step) ----
        if (t < T_STEPS - 1) {
            __syncthreads();
            if (tid == 0) {
                int* slot = bar + t;
                asm volatile("red.release.gpu.global.add.s32 [%0], 1;" :: "l"(slot) : "memory");
                int v;
                do {
                    __nanosleep(64);
                    asm volatile("ld.acquire.gpu.global.b32 %0, [%1];" : "=r"(v) : "l"(slot) : "memory");
                } while (v < 128);
            }
            __syncthreads();
        }
    }
}

// =====================================================================
// Precompute kernel: Z = xs @ W1x + b1, fp32 via bf16 3-term HMMA.
// =====================================================================
__global__ void __launch_bounds__(256, 1)
pre_hmma(const __nv_bfloat16* __restrict__ xs_hi, const __nv_bfloat16* __restrict__ xs_lo,
         const __nv_bfloat16* __restrict__ wx_hi, const __nv_bfloat16* __restrict__ wx_lo,
         const float* __restrict__ b1, float* __restrict__ Z) {
    extern __shared__ __align__(128) char pool[];   // 3 x (16KB A + 8KB B)

    const int tid = threadIdx.x;
    const int w = tid >> 5;
    const int lane = tid & 31;
    const int mw = w & 3, nw = w >> 2;
    const int n0 = blockIdx.x * 64;
    const int m0 = blockIdx.y * 128;

    auto sA = [&](int buf) { return smem_u32(pool) + buf * 16384; };
    auto sB = [&](int buf) { return smem_u32(pool) + 49152 + buf * 8192; };

    auto issue = [&](int kt, int buf) {
        const int seg = kt >> 2;
        const int k0 = (kt & 3) << 6;
        const __nv_bfloat16* Ap = (seg == 1) ? xs_lo : xs_hi;
        const __nv_bfloat16* Bp = (seg == 2) ? wx_lo : wx_hi;
        const uint32_t a = sA(buf), b = sB(buf);
#pragma unroll
        for (int i = 0; i < 4; i++) {
            const int c = tid + (i << 8);
            const int row = c >> 3, kb = (c & 7) << 4;
            cp_async16(a + row * 128 + (kb ^ ((row & 7) << 4)),
                       (const char*)(Ap + (size_t)(m0 + row) * DIN + k0) + kb);
        }
#pragma unroll
        for (int i = 0; i < 2; i++) {
            const int c = tid + (i << 8);
            const int row = c >> 3, kb = (c & 7) << 4;
            cp_async16(b + row * 128 + (kb ^ ((row & 7) << 4)),
                       (const char*)(Bp + (size_t)(n0 + row) * DIN + k0) + kb);
        }
    };

    const int l7 = lane & 7;
    const uint32_t xmk = (uint32_t)(l7 << 4);
    const int rowA = ((lane >> 3) & 1) * 8 + l7;
    const uint32_t kselA = ((lane >> 4) & 1) * 16;
    const int rowBb = ((lane >> 4) & 1) * 8 + l7;
    const uint32_t kselB = ((lane >> 3) & 1) * 16;

    float acc[2][4][4];
#pragma unroll
    for (int mt = 0; mt < 2; mt++)
#pragma unroll
        for (int n8 = 0; n8 < 4; n8++)
#pragma unroll
            for (int q = 0; q < 4; q++) acc[mt][n8][q] = 0.0f;

    auto compute = [&](int buf) {
        const uint32_t a = sA(buf), b = sB(buf);
#pragma unroll
        for (int k16 = 0; k16 < 4; k16++) {
            const uint32_t kb = (uint32_t)(k16 * 32);
            uint32_t af[2][4];
#pragma unroll
            for (int mt = 0; mt < 2; mt++)
                ldmatrix_x4(af[mt],
                            a + (mw * 32 + mt * 16 + rowA) * 128 + ((kb + kselA) ^ xmk));
#pragma unroll
            for (int nt = 0; nt < 2; nt++) {
                uint32_t bf[4];
                ldmatrix_x4(bf,
                            b + (nw * 32 + nt * 16 + rowBb) * 128 + ((kb + kselB) ^ xmk));
#pragma unroll
                for (int mt = 0; mt < 2; mt++) {
                    mma_bf16(acc[mt][nt * 2],     af[mt], bf[0], bf[1]);
                    mma_bf16(acc[mt][nt * 2 + 1], af[mt], bf[2], bf[3]);
                }
            }
        }
    };

    issue(0, 0); cp_commit();
    issue(1, 1); cp_commit();
    for (int kt = 0; kt < 12; kt++) {
        cp_wait1();
        __syncthreads();
        if (kt + 2 < 12) issue(kt + 2, (kt + 2) % 3);
        cp_commit();
        compute(kt % 3);
    }

    const int g = lane >> 2, t4 = lane & 3;
#pragma unroll
    for (int mt = 0; mt < 2; mt++)
#pragma unroll
        for (int n8 = 0; n8 < 4; n8++) {
            const float* c = acc[mt][n8];
            const int col = n0 + nw * 32 + n8 * 8 + 2 * t4;
            const int r0 = m0 + mw * 32 + mt * 16 + g;
            const size_t o0 = (size_t)r0 * DH + col;
            const size_t o1 = o0 + 8 * DH;
            float2 bi = *reinterpret_cast<const float2*>(b1 + col);
            *reinterpret_cast<float2*>(Z + o0) = make_float2(c[0] + bi.x, c[1] + bi.y);
            *reinterpret_cast<float2*>(Z + o1) = make_float2(c[2] + bi.x, c[3] + bi.y);
        }
}

// ---------------- packed f32x2 GEMM (readout only) ----------------
__device__ __forceinline__ void fma2(unsigned long long& acc,
                                     unsigned long long a, unsigned long long b) {
    asm("fma.rn.f32x2 %0, %1, %2, %0;" : "+l"(acc) : "l"(a), "l"(b));
}
__device__ __forceinline__ unsigned long long pack2(float x, float y) {
    unsigned long long r;
    asm("mov.b64 %0, {%1, %2};" : "=l"(r) : "f"(x), "f"(y));
    return r;
}
__device__ __forceinline__ float2 unpack2(unsigned long long v) {
    float2 f;
    asm("mov.b64 {%0, %1}, %2;" : "=f"(f.x), "=f"(f.y) : "l"(v));
    return f;
}

template <int BM, int BN, int BK, int TM>
__global__ void __launch_bounds__(256)
gemm_f32x2(const float* __restrict__ A, const float* __restrict__ Bm,
           const float* __restrict__ aux, float* __restrict__ C,
           int M, int N, int K) {
    constexpr int TN = 4;
    constexpr int NT = (BM / TM) * (BN / TN);
    static_assert(NT == 256, "block must be 256 threads");
    __shared__ float As[BK][BM + 4];
    __shared__ float Bs[BK][BN];

    const int tid = threadIdx.x;
    const int n0 = blockIdx.x * BN;
    const int m0 = blockIdx.y * BM;
    constexpr int A_PER = (BM * BK / 4) / NT;
    constexpr int B_PER = (BK * BN / 4) / NT;
    float4 ar[A_PER], br[B_PER];

    auto loadA = [&](int kt) {
#pragma unroll
        for (int i = 0; i < A_PER; i++) {
            int idx = tid + i * NT, row = idx / (BK / 4), kc = idx % (BK / 4);
            ar[i] = *reinterpret_cast<const float4*>(&A[(size_t)(m0 + row) * K + kt * BK + kc * 4]);
        }
    };
    auto storeA = [&]() {
#pragma unroll
        for (int i = 0; i < A_PER; i++) {
            int idx = tid + i * NT, row = idx / (BK / 4), kc = idx % (BK / 4);
            As[kc * 4 + 0][row] = ar[i].x; As[kc * 4 + 1][row] = ar[i].y;
            As[kc * 4 + 2][row] = ar[i].z; As[kc * 4 + 3][row] = ar[i].w;
        }
    };
    auto loadB = [&](int kt) {
#pragma unroll
        for (int i = 0; i < B_PER; i++) {
            int idx = tid + i * NT, kr = idx / (BN / 4), nc = idx % (BN / 4);
            br[i] = *reinterpret_cast<const float4*>(&Bm[(size_t)(kt * BK + kr) * N + n0 + nc * 4]);
        }
    };
    auto storeB = [&]() {
#pragma unroll
        for (int i = 0; i < B_PER; i++) {
            int idx = tid + i * NT, kr = idx / (BN / 4), nc = idx % (BN / 4);
            *reinterpret_cast<float4*>(&Bs[kr][nc * 4]) = br[i];
        }
    };

    unsigned long long acc[TM][2];
#pragma unroll
    for (int i = 0; i < TM; i++) { acc[i][0] = pack2(0, 0); acc[i][1] = pack2(0, 0); }

    const int rg = tid / (BN / TN), cg = tid % (BN / TN);
    const int r0 = rg * TM, c0 = cg * TN;
    const int nk = K / BK;
    loadA(0); loadB(0); storeA(); storeB();
    __syncthreads();
    for (int kt = 0; kt < nk; kt++) {
        if (kt + 1 < nk) { loadA(kt + 1); loadB(kt + 1); }
#pragma unroll
        for (int k = 0; k < BK; k++) {
            float a[TM];
            if (TM == 2) {
                float2 avv = *reinterpret_cast<const float2*>(&As[k][r0]);
                a[0] = avv.x; a[1] = avv.y;
            } else {
                float4 avv = *reinterpret_cast<const float4*>(&As[k][r0]);
                a[0] = avv.x; a[1] = avv.y; a[2] = avv.z; a[3] = avv.w;
            }
            float4 bvv = *reinterpret_cast<const float4*>(&Bs[k][c0]);
            unsigned long long b01 = pack2(bvv.x, bvv.y), b23 = pack2(bvv.z, bvv.w);
#pragma unroll
            for (int i = 0; i < TM; i++) {
                unsigned long long aa = pack2(a[i], a[i]);
                fma2(acc[i][0], aa, b01);
                fma2(acc[i][1], aa, b23);
            }
        }
        __syncthreads();
        if (kt + 1 < nk) { storeA(); storeB(); __syncthreads(); }
    }
#pragma unroll
    for (int i = 0; i < TM; i++) {
        float2 p0 = unpack2(acc[i][0]), p1 = unpack2(acc[i][1]);
        float4 v = make_float4(p0.x, p0.y, p1.x, p1.y);
        const int row = m0 + r0 + i, col = n0 + c0;
        const size_t off = (size_t)row * N + col;
        float s = aux[0];
        v.x += s; v.y += s; v.z += s; v.w += s;
        *reinterpret_cast<float4*>(&C[off]) = v;
    }
}

// ---------------- host launcher ----------------
extern "C" void kernel_launch(void* const* d_in, const int* in_sizes, int n_in,
                              void* d_out, int out_size) {
    const float* xs  = (const float*)d_in[0];
    const float* W1x = (const float*)d_in[1];
    const float* W1h = (const float*)d_in[2];
    const float* b1  = (const float*)d_in[3];
    const float* W2  = (const float*)d_in[4];
    const float* b2  = (const float*)d_in[5];
    float* out = (float*)d_out;

    float *zp, *hf;
    int* barp;
    __nv_bfloat16 *hhi, *hlo, *wthi, *wtlo, *xshi, *xslo, *wxhi, *wxlo;
    cudaGetSymbolAddress((void**)&zp, g_z);
    cudaGetSymbolAddress((void**)&hf, g_hf);
    cudaGetSymbolAddress((void**)&hhi, g_h_hi);
    cudaGetSymbolAddress((void**)&hlo, g_h_lo);
    cudaGetSymbolAddress((void**)&wthi, g_wt_hi);
    cudaGetSymbolAddress((void**)&wtlo, g_wt_lo);
    cudaGetSymbolAddress((void**)&xshi, g_xs_hi);
    cudaGetSymbolAddress((void**)&xslo, g_xs_lo);
    cudaGetSymbolAddress((void**)&wxhi, g_w1xt_hi);
    cudaGetSymbolAddress((void**)&wxlo, g_w1xt_lo);
    cudaGetSymbolAddress((void**)&barp, g_bar);

    cudaFuncSetAttribute(pre_hmma, cudaFuncAttributeMaxDynamicSharedMemorySize, 73728);
    cudaFuncSetAttribute(rnn_persist, cudaFuncAttributeMaxDynamicSharedMemorySize, SMEM_TOT);

    const size_t HS = (size_t)BATCH * DH;
    const int XN = T_STEPS * BATCH * DIN;

    // splits
    fsplit_kernel<<<XN / 4 / 256, 256>>>(xs, xshi, xslo, XN / 4);
    wsplit_kernel<<<dim3(DH / 32, DIN / 32), dim3(32, 8)>>>(W1x, wxhi, wxlo, DIN, DH);
    wsplit_kernel<<<dim3(DH / 32, DH / 32), dim3(32, 8)>>>(W1h, wthi, wtlo, DH, DH);

    // zero h ping-pong buffer 0 (hi + lo) and barrier slots
    zero_u4<<<(int)(HS / 8 / 256), 256>>>((uint4*)hhi, (int)(HS / 8));
    zero_u4<<<(int)(HS / 8 / 256), 256>>>((uint4*)hlo, (int)(HS / 8));
    zero_u4<<<1, 32>>>((uint4*)barp, T_STEPS / 4);

    // Z = xs@W1x + b1 (HMMA, 3-term)
    pre_hmma<<<dim3(16, 256), 256, 73728>>>(xshi, xslo, wxhi, wxlo, b1, zp);

    // full recurrence in one persistent launch (W resident in smem)
    rnn_persist<<<128, 256, SMEM_TOT>>>(hhi, hlo, wthi, wtlo, zp, hf, barp);

    // out = h_final @ W2 + b2
    gemm_f32x2<32, 64, 32, 2>
        <<<dim3(DOUT / 64, BATCH / 32), 256>>>(hf, W2, b2, out, BATCH, DOUT, DH);
}